// round 9
// baseline (speedup 1.0000x reference)
#include <cuda_runtime.h>
#include <cuda_bf16.h>
#include <cstdint>

#define NN 20000
#define DD 128
#define EE 32768
#define RR 474
#define BB 64
#define GB 32          // grouping blocks
#define GT 256         // grouping threads
#define EPB (EE / GB)  // 1024 edges per grouping block

// ---------------- device scratch ----------------
__device__ float g_X[NN * DD];
__device__ float g_H[NN * DD];
__device__ float g_W1[RR * DD * DD];
__device__ float g_W2[RR * DD * DD];
__device__ float g_alpha[EE];
__device__ float g_denom0[NN];
__device__ float g_denom1[NN];
__device__ int   g_bh[GB * RR];
__device__ int   g_bstart[GB * RR];
__device__ int   g_offs[RR + 1];
__device__ int   g_order[EE];

// ---------------- mma helpers ----------------
__device__ __forceinline__ void mma_bf16(float* d, const uint32_t* a, const uint32_t* b) {
    asm volatile(
        "mma.sync.aligned.m16n8k16.row.col.f32.bf16.bf16.f32 "
        "{%0,%1,%2,%3}, {%4,%5,%6,%7}, {%8,%9}, {%0,%1,%2,%3};"
        : "+f"(d[0]), "+f"(d[1]), "+f"(d[2]), "+f"(d[3])
        : "r"(a[0]), "r"(a[1]), "r"(a[2]), "r"(a[3]), "r"(b[0]), "r"(b[1]));
}
__device__ __forceinline__ uint32_t pack2_bf16(float a, float b) {
    __nv_bfloat162 p = __floats2bfloat162_rn(a, b);
    return *reinterpret_cast<uint32_t*>(&p);
}
__device__ __forceinline__ void split_bf16(float v, __nv_bfloat16& h, float& lo) {
    h = __float2bfloat16(v);
    lo = v - __bfloat162float(h);
}

// ================= W build: C[M,16384] = A[M,64] @ B[64,16384] =================
// v2: 64x128 tile, 256 threads (8 warps, 2x4), warp tile 32x32, 2 blocks/SM.
#define WB_STRIDE 72
#define WB_A_HI 0
#define WB_A_LO (64 * WB_STRIDE * 2)                 //  9216
#define WB_B_HI (2 * 64 * WB_STRIDE * 2)             // 18432
#define WB_B_LO (2 * 64 * WB_STRIDE * 2 + 128 * WB_STRIDE * 2)
#define WB_SMEM (2 * 64 * WB_STRIDE * 2 + 2 * 128 * WB_STRIDE * 2)  // 55296

__global__ void __launch_bounds__(256, 2)
k_wbuild(const float* __restrict__ A, const float* __restrict__ B,
         float* __restrict__ C, int M) {
    extern __shared__ char smem[];
    __nv_bfloat16* sAh = (__nv_bfloat16*)(smem + WB_A_HI);
    __nv_bfloat16* sAl = (__nv_bfloat16*)(smem + WB_A_LO);
    __nv_bfloat16* sBh = (__nv_bfloat16*)(smem + WB_B_HI);
    __nv_bfloat16* sBl = (__nv_bfloat16*)(smem + WB_B_LO);

    int t = threadIdx.x;
    int n0 = blockIdx.x * 128, m0 = blockIdx.y * 64;

    // stage A tile [64 x 64]
    #pragma unroll
    for (int e = t; e < 64 * 64; e += 256) {
        int m = e >> 6, k = e & 63;
        float v = (m0 + m < M) ? A[(m0 + m) * 64 + k] : 0.f;
        __nv_bfloat16 h; float lo;
        split_bf16(v, h, lo);
        sAh[m * WB_STRIDE + k] = h;
        sAl[m * WB_STRIDE + k] = __float2bfloat16(lo);
    }
    // stage B^T tile [128 n x 64 k]
    #pragma unroll
    for (int e = t; e < 64 * 128; e += 256) {
        int k = e >> 7, n = e & 127;
        float v = B[(size_t)k * 16384 + n0 + n];
        __nv_bfloat16 h; float lo;
        split_bf16(v, h, lo);
        sBh[n * WB_STRIDE + k] = h;
        sBl[n * WB_STRIDE + k] = __float2bfloat16(lo);
    }
    __syncthreads();

    int wid = t >> 5, lane = t & 31;
    int warpM = wid >> 2, warpN = wid & 3;   // 2 x 4, warp tile 32x32
    int g = lane >> 2, tg = lane & 3;

    float acc[2][4][4];
    #pragma unroll
    for (int i = 0; i < 2; i++)
        #pragma unroll
        for (int j = 0; j < 4; j++)
            #pragma unroll
            for (int q = 0; q < 4; q++) acc[i][j][q] = 0.f;

    #pragma unroll
    for (int ks = 0; ks < 4; ks++) {
        int kk = ks * 16 + tg * 2;
        uint32_t ah[2][4], al[2][4];
        #pragma unroll
        for (int mt = 0; mt < 2; mt++) {
            int r0 = warpM * 32 + mt * 16 + g;
            ah[mt][0] = *(const uint32_t*)&sAh[r0 * WB_STRIDE + kk];
            ah[mt][1] = *(const uint32_t*)&sAh[(r0 + 8) * WB_STRIDE + kk];
            ah[mt][2] = *(const uint32_t*)&sAh[r0 * WB_STRIDE + kk + 8];
            ah[mt][3] = *(const uint32_t*)&sAh[(r0 + 8) * WB_STRIDE + kk + 8];
            al[mt][0] = *(const uint32_t*)&sAl[r0 * WB_STRIDE + kk];
            al[mt][1] = *(const uint32_t*)&sAl[(r0 + 8) * WB_STRIDE + kk];
            al[mt][2] = *(const uint32_t*)&sAl[r0 * WB_STRIDE + kk + 8];
            al[mt][3] = *(const uint32_t*)&sAl[(r0 + 8) * WB_STRIDE + kk + 8];
        }
        uint32_t bh[4][2], bl[4][2];
        #pragma unroll
        for (int nt = 0; nt < 4; nt++) {
            int nb = warpN * 32 + nt * 8 + g;
            bh[nt][0] = *(const uint32_t*)&sBh[nb * WB_STRIDE + kk];
            bh[nt][1] = *(const uint32_t*)&sBh[nb * WB_STRIDE + kk + 8];
            bl[nt][0] = *(const uint32_t*)&sBl[nb * WB_STRIDE + kk];
            bl[nt][1] = *(const uint32_t*)&sBl[nb * WB_STRIDE + kk + 8];
        }
        #pragma unroll
        for (int mt = 0; mt < 2; mt++)
            #pragma unroll
            for (int nt = 0; nt < 4; nt++) {
                mma_bf16(acc[mt][nt], ah[mt], bh[nt]);
                mma_bf16(acc[mt][nt], ah[mt], bl[nt]);
                mma_bf16(acc[mt][nt], al[mt], bh[nt]);
            }
    }

    #pragma unroll
    for (int mt = 0; mt < 2; mt++) {
        int r0 = m0 + warpM * 32 + mt * 16 + g;
        #pragma unroll
        for (int nt = 0; nt < 4; nt++) {
            int col = n0 + warpN * 32 + nt * 8 + tg * 2;
            if (r0 < M)
                *(float2*)&C[(size_t)r0 * 16384 + col] = make_float2(acc[mt][nt][0], acc[mt][nt][1]);
            if (r0 + 8 < M)
                *(float2*)&C[(size_t)(r0 + 8) * 16384 + col] = make_float2(acc[mt][nt][2], acc[mt][nt][3]);
        }
    }
}

// ================= root GEMM: C[M,128] = A[M,128] @ Broot + bias (optional relu on A) ======
#define RT_STRIDE 136
__global__ void __launch_bounds__(128, 4)
k_root(const float* __restrict__ A, const float* __restrict__ Broot,
       const float* __restrict__ bias, float* __restrict__ C, int M, int relu_in) {
    int n_base = blockIdx.x * 64;
    int m0 = blockIdx.y * 64;
    int t = threadIdx.x, wid = t >> 5, lane = t & 31;
    int g = lane >> 2, tg = lane & 3;

    uint32_t bhf[2][8][2], blf[2][8][2];
    #pragma unroll
    for (int nt = 0; nt < 2; nt++) {
        int n = n_base + wid * 16 + nt * 8 + g;
        #pragma unroll
        for (int s = 0; s < 8; s++) {
            int k0 = s * 16 + tg * 2;
            float w0 = Broot[(k0 + 0) * 128 + n];
            float w1 = Broot[(k0 + 1) * 128 + n];
            float w2 = Broot[(k0 + 8) * 128 + n];
            float w3 = Broot[(k0 + 9) * 128 + n];
            __nv_bfloat16 h0, h1, h2, h3; float l0, l1, l2, l3;
            split_bf16(w0, h0, l0); split_bf16(w1, h1, l1);
            split_bf16(w2, h2, l2); split_bf16(w3, h3, l3);
            bhf[nt][s][0] = pack2_bf16(__bfloat162float(h0), __bfloat162float(h1));
            bhf[nt][s][1] = pack2_bf16(__bfloat162float(h2), __bfloat162float(h3));
            blf[nt][s][0] = pack2_bf16(l0, l1);
            blf[nt][s][1] = pack2_bf16(l2, l3);
        }
    }

    __shared__ __align__(16) __nv_bfloat16 s_ah[64][RT_STRIDE];
    __shared__ __align__(16) __nv_bfloat16 s_al[64][RT_STRIDE];

    #pragma unroll
    for (int e = t; e < 64 * 128; e += 128) {
        int row = e >> 7, col = e & 127;
        float v = (m0 + row < M) ? A[(size_t)(m0 + row) * 128 + col] : 0.f;
        if (relu_in) v = fmaxf(v, 0.f);
        __nv_bfloat16 h; float lo;
        split_bf16(v, h, lo);
        s_ah[row][col] = h;
        s_al[row][col] = __float2bfloat16(lo);
    }
    __syncthreads();

    float2 biasv[2];
    #pragma unroll
    for (int nt = 0; nt < 2; nt++) {
        int col = n_base + wid * 16 + nt * 8 + tg * 2;
        biasv[nt] = make_float2(bias[col], bias[col + 1]);
    }

    #pragma unroll
    for (int mt = 0; mt < 4; mt++) {
        float acc[2][4];
        #pragma unroll
        for (int nt = 0; nt < 2; nt++)
            #pragma unroll
            for (int q = 0; q < 4; q++) acc[nt][q] = 0.f;

        int ar = mt * 16 + g;
        #pragma unroll
        for (int s = 0; s < 8; s++) {
            int k0 = s * 16 + tg * 2;
            uint32_t ah[4], al[4];
            ah[0] = *(const uint32_t*)&s_ah[ar][k0];
            ah[1] = *(const uint32_t*)&s_ah[ar + 8][k0];
            ah[2] = *(const uint32_t*)&s_ah[ar][k0 + 8];
            ah[3] = *(const uint32_t*)&s_ah[ar + 8][k0 + 8];
            al[0] = *(const uint32_t*)&s_al[ar][k0];
            al[1] = *(const uint32_t*)&s_al[ar + 8][k0];
            al[2] = *(const uint32_t*)&s_al[ar][k0 + 8];
            al[3] = *(const uint32_t*)&s_al[ar + 8][k0 + 8];
            #pragma unroll
            for (int nt = 0; nt < 2; nt++) {
                mma_bf16(acc[nt], ah, bhf[nt][s]);
                mma_bf16(acc[nt], ah, blf[nt][s]);
                mma_bf16(acc[nt], al, bhf[nt][s]);
            }
        }

        int r0 = m0 + mt * 16 + g, r1 = r0 + 8;
        #pragma unroll
        for (int nt = 0; nt < 2; nt++) {
            int col = n_base + wid * 16 + nt * 8 + tg * 2;
            if (r0 < M)
                *(float2*)&C[(size_t)r0 * 128 + col] =
                    make_float2(acc[nt][0] + biasv[nt].x, acc[nt][1] + biasv[nt].y);
            if (r1 < M)
                *(float2*)&C[(size_t)r1 * 128 + col] =
                    make_float2(acc[nt][2] + biasv[nt].x, acc[nt][3] + biasv[nt].y);
        }
    }
}

// ---------------- gather + denom init ----------------
__global__ void k_gather_init(const int* __restrict__ entity, const float* __restrict__ emb) {
    int g = blockIdx.x * blockDim.x + threadIdx.x;
    if (g < NN) { g_denom0[g] = 0.f; g_denom1[g] = 0.f; }
    if (g >= NN * DD / 4) return;
    int elem = g * 4;
    int n = elem >> 7, d = elem & 127;
    int idx = entity[n];
    *(float4*)&g_X[elem] = *(const float4*)&emb[idx * DD + d];
}

// ---------------- grouping: smem counting sort ----------------
__global__ void k_hist(const int* __restrict__ etype) {
    __shared__ int h[RR];
    int t = threadIdx.x, b = blockIdx.x;
    for (int i = t; i < RR; i += GT) h[i] = 0;
    __syncthreads();
    int base = b * EPB;
    for (int i = t; i < EPB; i += GT) atomicAdd(&h[etype[base + i]], 1);
    __syncthreads();
    for (int i = t; i < RR; i += GT) g_bh[b * RR + i] = h[i];
}

__global__ void k_scan2() {
    __shared__ int tot[512];
    int t = threadIdx.x;
    int sum = 0;
    if (t < RR) {
        #pragma unroll 8
        for (int b = 0; b < GB; b++) sum += g_bh[b * RR + t];
    }
    tot[t] = (t < RR) ? sum : 0;
    __syncthreads();
    #pragma unroll
    for (int off = 1; off < 512; off <<= 1) {
        int v = (t >= off) ? tot[t - off] : 0;
        __syncthreads();
        tot[t] += v;
        __syncthreads();
    }
    if (t < RR) {
        g_offs[t + 1] = tot[t];
        int run = tot[t] - sum;
        for (int b = 0; b < GB; b++) {
            g_bstart[b * RR + t] = run;
            run += g_bh[b * RR + t];
        }
    }
    if (t == 0) g_offs[0] = 0;
}

__global__ void k_place(const int* __restrict__ etype) {
    __shared__ int cur[RR];
    int t = threadIdx.x, b = blockIdx.x;
    for (int i = t; i < RR; i += GT) cur[i] = g_bstart[b * RR + i];
    __syncthreads();
    int base = b * EPB;
    for (int i = t; i < EPB; i += GT) {
        int e = base + i;
        int p = atomicAdd(&cur[etype[e]], 1);
        g_order[p] = e;
    }
}

// ---------------- fused logits+exp+denom (no max pass: |logit| small) ----------------
__global__ void k_alpha_exp(const float* __restrict__ X, const int* __restrict__ src,
                            const int* __restrict__ dst, const int* __restrict__ etype,
                            const float* __restrict__ wt, float* __restrict__ denom,
                            int relu_in) {
    int e = blockIdx.x * (blockDim.x >> 5) + (threadIdx.x >> 5);
    if (e >= EE) return;
    int lane = threadIdx.x & 31;
    int s = src[e], d = dst[e], r = etype[e];
    float4 xi = *(const float4*)&X[d * DD + lane * 4];
    float4 xj = *(const float4*)&X[s * DD + lane * 4];
    if (relu_in) {
        xi.x = fmaxf(xi.x, 0.f); xi.y = fmaxf(xi.y, 0.f);
        xi.z = fmaxf(xi.z, 0.f); xi.w = fmaxf(xi.w, 0.f);
        xj.x = fmaxf(xj.x, 0.f); xj.y = fmaxf(xj.y, 0.f);
        xj.z = fmaxf(xj.z, 0.f); xj.w = fmaxf(xj.w, 0.f);
    }
    float4 w  = *(const float4*)&wt[r * DD + lane * 4];
    float v = xi.x * w.x * xj.x + xi.y * w.y * xj.y + xi.z * w.z * xj.z + xi.w * w.w * xj.w;
    #pragma unroll
    for (int off = 16; off; off >>= 1) v += __shfl_xor_sync(0xffffffffu, v, off);
    if (lane == 0) {
        float a = expf(v);
        g_alpha[e] = a;
        atomicAdd(&denom[d], a);
    }
}

// ---------------- per-type messages on tensor cores ----------------
#define MSG_STRIDE 136
__global__ void __launch_bounds__(256, 2)
k_msg(const float* __restrict__ Xin, float* __restrict__ Y,
      const int* __restrict__ srcArr, const int* __restrict__ dstArr,
      const float* __restrict__ denom, int relu_in, const float* __restrict__ Wbuf) {
    int r = blockIdx.x;
    int base = g_offs[r];
    int cnt = g_offs[r + 1] - base;
    if (cnt == 0) return;
    int t = threadIdx.x, wid = t >> 5, lane = t & 31;
    int g = lane >> 2, tg = lane & 3;

    const float* Wr = Wbuf + (size_t)r * 16384;
    uint32_t bhf[2][8][2], blf[2][8][2];
    #pragma unroll
    for (int nt = 0; nt < 2; nt++) {
        int n = wid * 16 + nt * 8 + g;
        #pragma unroll
        for (int s = 0; s < 8; s++) {
            int k0 = s * 16 + tg * 2;
            float w0 = Wr[(k0 + 0) * 128 + n];
            float w1 = Wr[(k0 + 1) * 128 + n];
            float w2 = Wr[(k0 + 8) * 128 + n];
            float w3 = Wr[(k0 + 9) * 128 + n];
            __nv_bfloat16 h0, h1, h2, h3; float l0, l1, l2, l3;
            split_bf16(w0, h0, l0); split_bf16(w1, h1, l1);
            split_bf16(w2, h2, l2); split_bf16(w3, h3, l3);
            bhf[nt][s][0] = pack2_bf16(__bfloat162float(h0), __bfloat162float(h1));
            bhf[nt][s][1] = pack2_bf16(__bfloat162float(h2), __bfloat162float(h3));
            blf[nt][s][0] = pack2_bf16(l0, l1);
            blf[nt][s][1] = pack2_bf16(l2, l3);
        }
    }

    __shared__ __align__(16) __nv_bfloat16 s_xh[16][MSG_STRIDE];
    __shared__ __align__(16) __nv_bfloat16 s_xl[16][MSG_STRIDE];
    __shared__ int   dsts[16];
    __shared__ int   srcs[16];
    __shared__ float scl[16];

    for (int g0 = 0; g0 < cnt; g0 += 16) {
        __syncthreads();
        if (t < 16) {
            int j = g0 + t;
            if (j < cnt) {
                int e = g_order[base + j];
                int d = dstArr[e];
                dsts[t] = d;
                srcs[t] = srcArr[e];
                scl[t]  = g_alpha[e] / denom[d];
            } else { dsts[t] = -1; srcs[t] = 0; scl[t] = 0.f; }
        }
        __syncthreads();
        #pragma unroll
        for (int j2 = 0; j2 < 16; j2 += 2) {
            int j = j2 + (t >> 7);
            int i = t & 127;
            float v = Xin[(size_t)srcs[j] * DD + i];
            if (relu_in) v = fmaxf(v, 0.f);
            v *= scl[j];
            __nv_bfloat16 h; float lo;
            split_bf16(v, h, lo);
            s_xh[j][i] = h;
            s_xl[j][i] = __float2bfloat16(lo);
        }
        __syncthreads();

        float acc[2][4];
        #pragma unroll
        for (int nt = 0; nt < 2; nt++)
            #pragma unroll
            for (int q = 0; q < 4; q++) acc[nt][q] = 0.f;

        #pragma unroll
        for (int s = 0; s < 8; s++) {
            int k0 = s * 16 + tg * 2;
            uint32_t ah[4], al[4];
            ah[0] = *(const uint32_t*)&s_xh[g][k0];
            ah[1] = *(const uint32_t*)&s_xh[g + 8][k0];
            ah[2] = *(const uint32_t*)&s_xh[g][k0 + 8];
            ah[3] = *(const uint32_t*)&s_xh[g + 8][k0 + 8];
            al[0] = *(const uint32_t*)&s_xl[g][k0];
            al[1] = *(const uint32_t*)&s_xl[g + 8][k0];
            al[2] = *(const uint32_t*)&s_xl[g][k0 + 8];
            al[3] = *(const uint32_t*)&s_xl[g + 8][k0 + 8];
            #pragma unroll
            for (int nt = 0; nt < 2; nt++) {
                mma_bf16(acc[nt], ah, bhf[nt][s]);
                mma_bf16(acc[nt], ah, blf[nt][s]);
                mma_bf16(acc[nt], al, bhf[nt][s]);
            }
        }

        int d0 = dsts[g], d1 = dsts[g + 8];
        #pragma unroll
        for (int nt = 0; nt < 2; nt++) {
            int col = wid * 16 + nt * 8 + tg * 2;
            if (d0 >= 0) {
                atomicAdd(&Y[(size_t)d0 * DD + col],     acc[nt][0]);
                atomicAdd(&Y[(size_t)d0 * DD + col + 1], acc[nt][1]);
            }
            if (d1 >= 0) {
                atomicAdd(&Y[(size_t)d1 * DD + col],     acc[nt][2]);
                atomicAdd(&Y[(size_t)d1 * DD + col + 1], acc[nt][3]);
            }
        }
    }
}

// ---------------- launcher (forked-stream graph) ----------------
extern "C" void kernel_launch(void* const* d_in, const int* in_sizes, int n_in,
                              void* d_out, int out_size) {
    const int*   entity = (const int*)d_in[0];
    const int*   eidx   = (const int*)d_in[1];
    const int*   etype  = (const int*)d_in[2];
    const float* emb    = (const float*)d_in[3];
    const float* basis1 = (const float*)d_in[4];
    const float* att1   = (const float*)d_in[5];
    const float* w1     = (const float*)d_in[6];
    const float* root1  = (const float*)d_in[7];
    const float* bias1  = (const float*)d_in[8];
    const float* basis2 = (const float*)d_in[9];
    const float* att2   = (const float*)d_in[10];
    const float* w2     = (const float*)d_in[11];
    const float* root2  = (const float*)d_in[12];
    const float* bias2  = (const float*)d_in[13];
    float* out = (float*)d_out;
    const int* src = eidx;
    const int* dst = eidx + EE;

    float *pX = nullptr, *pH = nullptr, *pW1 = nullptr, *pW2 = nullptr, *pD0 = nullptr, *pD1 = nullptr;
    cudaGetSymbolAddress((void**)&pX, g_X);
    cudaGetSymbolAddress((void**)&pH, g_H);
    cudaGetSymbolAddress((void**)&pW1, g_W1);
    cudaGetSymbolAddress((void**)&pW2, g_W2);
    cudaGetSymbolAddress((void**)&pD0, g_denom0);
    cudaGetSymbolAddress((void**)&pD1, g_denom1);

    cudaFuncSetAttribute(k_wbuild, cudaFuncAttributeMaxDynamicSharedMemorySize, WB_SMEM);

    const int NVEC = NN * DD / 4;
    const dim3 rootGrid(2, (NN + 63) / 64);

    cudaStream_t sA;
    cudaStreamCreateWithFlags(&sA, cudaStreamNonBlocking);
    cudaEvent_t evFork, evA1, evA2;
    cudaEventCreateWithFlags(&evFork, cudaEventDisableTiming);
    cudaEventCreateWithFlags(&evA1, cudaEventDisableTiming);
    cudaEventCreateWithFlags(&evA2, cudaEventDisableTiming);

    // fork branch A off the main (legacy) stream
    cudaEventRecord(evFork, 0);
    cudaStreamWaitEvent(sA, evFork, 0);

    // branch A: grouping + both W builds (independent of X)
    k_hist<<<GB, GT, 0, sA>>>(etype);
    k_scan2<<<1, 512, 0, sA>>>();
    k_place<<<GB, GT, 0, sA>>>(etype);
    k_wbuild<<<dim3(128, 8), 256, WB_SMEM, sA>>>(att1, basis1, pW1, RR);
    cudaEventRecord(evA1, sA);
    k_wbuild<<<dim3(128, 8), 256, WB_SMEM, sA>>>(att2, basis2, pW2, RR);
    cudaEventRecord(evA2, sA);

    // main stream: feature path
    k_gather_init<<<(NVEC + 255) / 256, 256>>>(entity, emb);
    k_alpha_exp<<<EE / 4, 128>>>(pX, src, dst, etype, w1, pD0, 0);
    k_root<<<rootGrid, 128>>>(pX, root1, bias1, pH, NN, 0);
    cudaStreamWaitEvent(0, evA1, 0);                  // join: grouping + W1 ready
    k_msg<<<RR, 256>>>(pX, pH, src, dst, pD0, 0, pW1);

    k_alpha_exp<<<EE / 4, 128>>>(pH, src, dst, etype, w2, pD1, 1);
    k_root<<<rootGrid, 128>>>(pH, root2, bias2, out, NN, 1);
    cudaStreamWaitEvent(0, evA2, 0);                  // join: W2 ready (full branch A joined)
    k_msg<<<RR, 256>>>(pH, out, src, dst, pD1, 1, pW2);
}

// round 10
// speedup vs baseline: 1.0410x; 1.0410x over previous
#include <cuda_runtime.h>
#include <cuda_bf16.h>
#include <cstdint>

#define NN 20000
#define DD 128
#define EE 32768
#define RR 474
#define BB 64
#define GB 32
#define GT 256
#define EPB (EE / GB)

// ---------------- device scratch ----------------
__device__ float g_X[NN * DD];
__device__ float g_H[NN * DD];
__device__ float g_W1[RR * DD * DD];
__device__ float g_W2[RR * DD * DD];
__device__ float g_alpha[EE];
__device__ float g_denom0[NN];
__device__ float g_denom1[NN];
__device__ int   g_bh[GB * RR];
__device__ int   g_bstart[GB * RR];
__device__ int   g_offs[RR + 1];
__device__ int   g_order[EE];

// ---------------- mma / ldmatrix helpers ----------------
__device__ __forceinline__ void mma_bf16(float* d, const uint32_t* a, const uint32_t* b) {
    asm volatile(
        "mma.sync.aligned.m16n8k16.row.col.f32.bf16.bf16.f32 "
        "{%0,%1,%2,%3}, {%4,%5,%6,%7}, {%8,%9}, {%0,%1,%2,%3};"
        : "+f"(d[0]), "+f"(d[1]), "+f"(d[2]), "+f"(d[3])
        : "r"(a[0]), "r"(a[1]), "r"(a[2]), "r"(a[3]), "r"(b[0]), "r"(b[1]));
}
__device__ __forceinline__ void ldsm_x4(uint32_t* r, const void* p) {
    uint32_t addr = (uint32_t)__cvta_generic_to_shared(p);
    asm volatile("ldmatrix.sync.aligned.m8n8.x4.shared.b16 {%0,%1,%2,%3}, [%4];"
        : "=r"(r[0]), "=r"(r[1]), "=r"(r[2]), "=r"(r[3]) : "r"(addr));
}
__device__ __forceinline__ uint32_t pack2_bf16(float a, float b) {
    __nv_bfloat162 p = __floats2bfloat162_rn(a, b);
    return *reinterpret_cast<uint32_t*>(&p);
}
__device__ __forceinline__ void split_bf16(float v, __nv_bfloat16& h, float& lo) {
    h = __float2bfloat16(v);
    lo = v - __bfloat162float(h);
}

// ================= W build: C[M,16384] = A[M,64] @ B[64,16384] =================
// 64x128 tile, 8 warps (2x4), warp tile 32x32, ldmatrix fragment loads.
#define WB_STRIDE 72
#define WB_A_HI 0
#define WB_A_LO (64 * WB_STRIDE * 2)
#define WB_B_HI (2 * 64 * WB_STRIDE * 2)
#define WB_B_LO (2 * 64 * WB_STRIDE * 2 + 128 * WB_STRIDE * 2)
#define WB_SMEM (2 * 64 * WB_STRIDE * 2 + 2 * 128 * WB_STRIDE * 2)  // 55296

__global__ void __launch_bounds__(256, 2)
k_wbuild(const float* __restrict__ A, const float* __restrict__ B,
         float* __restrict__ C, int M) {
    extern __shared__ char smem[];
    __nv_bfloat16* sAh = (__nv_bfloat16*)(smem + WB_A_HI);
    __nv_bfloat16* sAl = (__nv_bfloat16*)(smem + WB_A_LO);
    __nv_bfloat16* sBh = (__nv_bfloat16*)(smem + WB_B_HI);
    __nv_bfloat16* sBl = (__nv_bfloat16*)(smem + WB_B_LO);

    int t = threadIdx.x;
    int n0 = blockIdx.x * 128, m0 = blockIdx.y * 64;

    #pragma unroll
    for (int e = t; e < 64 * 64; e += 256) {
        int m = e >> 6, k = e & 63;
        float v = (m0 + m < M) ? A[(m0 + m) * 64 + k] : 0.f;
        __nv_bfloat16 h; float lo;
        split_bf16(v, h, lo);
        sAh[m * WB_STRIDE + k] = h;
        sAl[m * WB_STRIDE + k] = __float2bfloat16(lo);
    }
    #pragma unroll
    for (int e = t; e < 64 * 128; e += 256) {
        int k = e >> 7, n = e & 127;
        float v = B[(size_t)k * 16384 + n0 + n];
        __nv_bfloat16 h; float lo;
        split_bf16(v, h, lo);
        sBh[n * WB_STRIDE + k] = h;
        sBl[n * WB_STRIDE + k] = __float2bfloat16(lo);
    }
    __syncthreads();

    int wid = t >> 5, lane = t & 31;
    int warpM = wid >> 2, warpN = wid & 3;
    int g = lane >> 2, tg = lane & 3;

    // ldmatrix address components
    int aRow = (lane & 15);
    int aColSel = ((lane >> 4) << 3);                 // 0 or 8
    int bN = ((lane >> 4) << 3) + (lane & 7);         // 0..15 within 16-row pair
    int bKSel = (((lane >> 3) & 1) << 3);             // 0 or 8

    float acc[2][4][4];
    #pragma unroll
    for (int i = 0; i < 2; i++)
        #pragma unroll
        for (int j = 0; j < 4; j++)
            #pragma unroll
            for (int q = 0; q < 4; q++) acc[i][j][q] = 0.f;

    #pragma unroll
    for (int ks = 0; ks < 4; ks++) {
        int k0 = ks * 16;
        uint32_t ah[2][4], al[2][4];
        #pragma unroll
        for (int mt = 0; mt < 2; mt++) {
            int row = warpM * 32 + mt * 16 + aRow;
            ldsm_x4(ah[mt], &sAh[row * WB_STRIDE + k0 + aColSel]);
            ldsm_x4(al[mt], &sAl[row * WB_STRIDE + k0 + aColSel]);
        }
        uint32_t bh[4][2], bl[4][2];
        #pragma unroll
        for (int np = 0; np < 2; np++) {
            int n = warpN * 32 + np * 16 + bN;
            uint32_t tmp[4];
            ldsm_x4(tmp, &sBh[n * WB_STRIDE + k0 + bKSel]);
            bh[np * 2][0] = tmp[0]; bh[np * 2][1] = tmp[1];
            bh[np * 2 + 1][0] = tmp[2]; bh[np * 2 + 1][1] = tmp[3];
            ldsm_x4(tmp, &sBl[n * WB_STRIDE + k0 + bKSel]);
            bl[np * 2][0] = tmp[0]; bl[np * 2][1] = tmp[1];
            bl[np * 2 + 1][0] = tmp[2]; bl[np * 2 + 1][1] = tmp[3];
        }
        #pragma unroll
        for (int mt = 0; mt < 2; mt++)
            #pragma unroll
            for (int nt = 0; nt < 4; nt++) {
                mma_bf16(acc[mt][nt], ah[mt], bh[nt]);
                mma_bf16(acc[mt][nt], ah[mt], bl[nt]);
                mma_bf16(acc[mt][nt], al[mt], bh[nt]);
            }
    }

    #pragma unroll
    for (int mt = 0; mt < 2; mt++) {
        int r0 = m0 + warpM * 32 + mt * 16 + g;
        #pragma unroll
        for (int nt = 0; nt < 4; nt++) {
            int col = n0 + warpN * 32 + nt * 8 + tg * 2;
            if (r0 < M)
                *(float2*)&C[(size_t)r0 * 16384 + col] = make_float2(acc[mt][nt][0], acc[mt][nt][1]);
            if (r0 + 8 < M)
                *(float2*)&C[(size_t)(r0 + 8) * 16384 + col] = make_float2(acc[mt][nt][2], acc[mt][nt][3]);
        }
    }
}

// ================= root GEMM: C[M,128] = A[M,128] @ Broot + bias =================
#define RT_STRIDE 136
__global__ void __launch_bounds__(128, 4)
k_root(const float* __restrict__ A, const float* __restrict__ Broot,
       const float* __restrict__ bias, float* __restrict__ C, int M, int relu_in) {
    int n_base = blockIdx.x * 64;
    int m0 = blockIdx.y * 64;
    int t = threadIdx.x, wid = t >> 5, lane = t & 31;
    int g = lane >> 2, tg = lane & 3;

    uint32_t bhf[2][8][2], blf[2][8][2];
    #pragma unroll
    for (int nt = 0; nt < 2; nt++) {
        int n = n_base + wid * 16 + nt * 8 + g;
        #pragma unroll
        for (int s = 0; s < 8; s++) {
            int k0 = s * 16 + tg * 2;
            float w0 = Broot[(k0 + 0) * 128 + n];
            float w1 = Broot[(k0 + 1) * 128 + n];
            float w2 = Broot[(k0 + 8) * 128 + n];
            float w3 = Broot[(k0 + 9) * 128 + n];
            __nv_bfloat16 h0, h1, h2, h3; float l0, l1, l2, l3;
            split_bf16(w0, h0, l0); split_bf16(w1, h1, l1);
            split_bf16(w2, h2, l2); split_bf16(w3, h3, l3);
            bhf[nt][s][0] = pack2_bf16(__bfloat162float(h0), __bfloat162float(h1));
            bhf[nt][s][1] = pack2_bf16(__bfloat162float(h2), __bfloat162float(h3));
            blf[nt][s][0] = pack2_bf16(l0, l1);
            blf[nt][s][1] = pack2_bf16(l2, l3);
        }
    }

    __shared__ __align__(16) __nv_bfloat16 s_ah[64][RT_STRIDE];
    __shared__ __align__(16) __nv_bfloat16 s_al[64][RT_STRIDE];

    #pragma unroll
    for (int e = t; e < 64 * 128; e += 128) {
        int row = e >> 7, col = e & 127;
        float v = (m0 + row < M) ? A[(size_t)(m0 + row) * 128 + col] : 0.f;
        if (relu_in) v = fmaxf(v, 0.f);
        __nv_bfloat16 h; float lo;
        split_bf16(v, h, lo);
        s_ah[row][col] = h;
        s_al[row][col] = __float2bfloat16(lo);
    }
    __syncthreads();

    float2 biasv[2];
    #pragma unroll
    for (int nt = 0; nt < 2; nt++) {
        int col = n_base + wid * 16 + nt * 8 + tg * 2;
        biasv[nt] = make_float2(bias[col], bias[col + 1]);
    }

    int aRow = (lane & 15);
    int aColSel = ((lane >> 4) << 3);

    #pragma unroll
    for (int mt = 0; mt < 4; mt++) {
        float acc[2][4];
        #pragma unroll
        for (int nt = 0; nt < 2; nt++)
            #pragma unroll
            for (int q = 0; q < 4; q++) acc[nt][q] = 0.f;

        #pragma unroll
        for (int s = 0; s < 8; s++) {
            int row = mt * 16 + aRow;
            int col = s * 16 + aColSel;
            uint32_t ah[4], al[4];
            ldsm_x4(ah, &s_ah[row][col]);
            ldsm_x4(al, &s_al[row][col]);
            #pragma unroll
            for (int nt = 0; nt < 2; nt++) {
                mma_bf16(acc[nt], ah, bhf[nt][s]);
                mma_bf16(acc[nt], ah, blf[nt][s]);
                mma_bf16(acc[nt], al, bhf[nt][s]);
            }
        }

        int r0 = m0 + mt * 16 + g, r1 = r0 + 8;
        #pragma unroll
        for (int nt = 0; nt < 2; nt++) {
            int col = n_base + wid * 16 + nt * 8 + tg * 2;
            if (r0 < M)
                *(float2*)&C[(size_t)r0 * 128 + col] =
                    make_float2(acc[nt][0] + biasv[nt].x, acc[nt][1] + biasv[nt].y);
            if (r1 < M)
                *(float2*)&C[(size_t)r1 * 128 + col] =
                    make_float2(acc[nt][2] + biasv[nt].x, acc[nt][3] + biasv[nt].y);
        }
    }
}

// ---------------- gather + denom init ----------------
__global__ void k_gather_init(const int* __restrict__ entity, const float* __restrict__ emb) {
    int g = blockIdx.x * blockDim.x + threadIdx.x;
    if (g < NN) { g_denom0[g] = 0.f; g_denom1[g] = 0.f; }
    if (g >= NN * DD / 4) return;
    int elem = g * 4;
    int n = elem >> 7, d = elem & 127;
    int idx = entity[n];
    *(float4*)&g_X[elem] = *(const float4*)&emb[idx * DD + d];
}

// ---------------- grouping: smem counting sort ----------------
__global__ void k_hist(const int* __restrict__ etype) {
    __shared__ int h[RR];
    int t = threadIdx.x, b = blockIdx.x;
    for (int i = t; i < RR; i += GT) h[i] = 0;
    __syncthreads();
    int base = b * EPB;
    for (int i = t; i < EPB; i += GT) atomicAdd(&h[etype[base + i]], 1);
    __syncthreads();
    for (int i = t; i < RR; i += GT) g_bh[b * RR + i] = h[i];
}

__global__ void k_scan2() {
    __shared__ int tot[512];
    int t = threadIdx.x;
    int sum = 0;
    if (t < RR) {
        #pragma unroll 8
        for (int b = 0; b < GB; b++) sum += g_bh[b * RR + t];
    }
    tot[t] = (t < RR) ? sum : 0;
    __syncthreads();
    #pragma unroll
    for (int off = 1; off < 512; off <<= 1) {
        int v = (t >= off) ? tot[t - off] : 0;
        __syncthreads();
        tot[t] += v;
        __syncthreads();
    }
    if (t < RR) {
        g_offs[t + 1] = tot[t];
        int run = tot[t] - sum;
        for (int b = 0; b < GB; b++) {
            g_bstart[b * RR + t] = run;
            run += g_bh[b * RR + t];
        }
    }
    if (t == 0) g_offs[0] = 0;
}

__global__ void k_place(const int* __restrict__ etype) {
    __shared__ int cur[RR];
    int t = threadIdx.x, b = blockIdx.x;
    for (int i = t; i < RR; i += GT) cur[i] = g_bstart[b * RR + i];
    __syncthreads();
    int base = b * EPB;
    for (int i = t; i < EPB; i += GT) {
        int e = base + i;
        int p = atomicAdd(&cur[etype[e]], 1);
        g_order[p] = e;
    }
}

// ---------------- fused logits+exp+denom ----------------
__global__ void k_alpha_exp(const float* __restrict__ X, const int* __restrict__ src,
                            const int* __restrict__ dst, const int* __restrict__ etype,
                            const float* __restrict__ wt, float* __restrict__ denom,
                            int relu_in) {
    int e = blockIdx.x * (blockDim.x >> 5) + (threadIdx.x >> 5);
    if (e >= EE) return;
    int lane = threadIdx.x & 31;
    int s = src[e], d = dst[e], r = etype[e];
    float4 xi = *(const float4*)&X[d * DD + lane * 4];
    float4 xj = *(const float4*)&X[s * DD + lane * 4];
    if (relu_in) {
        xi.x = fmaxf(xi.x, 0.f); xi.y = fmaxf(xi.y, 0.f);
        xi.z = fmaxf(xi.z, 0.f); xi.w = fmaxf(xi.w, 0.f);
        xj.x = fmaxf(xj.x, 0.f); xj.y = fmaxf(xj.y, 0.f);
        xj.z = fmaxf(xj.z, 0.f); xj.w = fmaxf(xj.w, 0.f);
    }
    float4 w  = *(const float4*)&wt[r * DD + lane * 4];
    float v = xi.x * w.x * xj.x + xi.y * w.y * xj.y + xi.z * w.z * xj.z + xi.w * w.w * xj.w;
    #pragma unroll
    for (int off = 16; off; off >>= 1) v += __shfl_xor_sync(0xffffffffu, v, off);
    if (lane == 0) {
        float a = expf(v);
        g_alpha[e] = a;
        atomicAdd(&denom[d], a);
    }
}

// ---------------- per-type messages on tensor cores ----------------
#define MSG_STRIDE 136
__global__ void __launch_bounds__(256, 2)
k_msg(const float* __restrict__ Xin, float* __restrict__ Y,
      const int* __restrict__ srcArr, const int* __restrict__ dstArr,
      const float* __restrict__ denom, int relu_in, const float* __restrict__ Wbuf) {
    int r = blockIdx.x;
    int base = g_offs[r];
    int cnt = g_offs[r + 1] - base;
    if (cnt == 0) return;
    int t = threadIdx.x, wid = t >> 5, lane = t & 31;
    int g = lane >> 2, tg = lane & 3;

    const float* Wr = Wbuf + (size_t)r * 16384;
    uint32_t bhf[2][8][2], blf[2][8][2];
    #pragma unroll
    for (int nt = 0; nt < 2; nt++) {
        int n = wid * 16 + nt * 8 + g;
        #pragma unroll
        for (int s = 0; s < 8; s++) {
            int k0 = s * 16 + tg * 2;
            float w0 = Wr[(k0 + 0) * 128 + n];
            float w1 = Wr[(k0 + 1) * 128 + n];
            float w2 = Wr[(k0 + 8) * 128 + n];
            float w3 = Wr[(k0 + 9) * 128 + n];
            __nv_bfloat16 h0, h1, h2, h3; float l0, l1, l2, l3;
            split_bf16(w0, h0, l0); split_bf16(w1, h1, l1);
            split_bf16(w2, h2, l2); split_bf16(w3, h3, l3);
            bhf[nt][s][0] = pack2_bf16(__bfloat162float(h0), __bfloat162float(h1));
            bhf[nt][s][1] = pack2_bf16(__bfloat162float(h2), __bfloat162float(h3));
            blf[nt][s][0] = pack2_bf16(l0, l1);
            blf[nt][s][1] = pack2_bf16(l2, l3);
        }
    }

    __shared__ __align__(16) __nv_bfloat16 s_xh[16][MSG_STRIDE];
    __shared__ __align__(16) __nv_bfloat16 s_xl[16][MSG_STRIDE];
    __shared__ int   dsts[16];
    __shared__ int   srcs[16];
    __shared__ float scl[16];

    int aRow = (lane & 15);
    int aColSel = ((lane >> 4) << 3);

    for (int g0 = 0; g0 < cnt; g0 += 16) {
        __syncthreads();
        if (t < 16) {
            int j = g0 + t;
            if (j < cnt) {
                int e = g_order[base + j];
                int d = dstArr[e];
                dsts[t] = d;
                srcs[t] = srcArr[e];
                scl[t]  = g_alpha[e] / denom[d];
            } else { dsts[t] = -1; srcs[t] = 0; scl[t] = 0.f; }
        }
        __syncthreads();
        #pragma unroll
        for (int j2 = 0; j2 < 16; j2 += 2) {
            int j = j2 + (t >> 7);
            int i = t & 127;
            float v = Xin[(size_t)srcs[j] * DD + i];
            if (relu_in) v = fmaxf(v, 0.f);
            v *= scl[j];
            __nv_bfloat16 h; float lo;
            split_bf16(v, h, lo);
            s_xh[j][i] = h;
            s_xl[j][i] = __float2bfloat16(lo);
        }
        __syncthreads();

        float acc[2][4];
        #pragma unroll
        for (int nt = 0; nt < 2; nt++)
            #pragma unroll
            for (int q = 0; q < 4; q++) acc[nt][q] = 0.f;

        #pragma unroll
        for (int s = 0; s < 8; s++) {
            int col = s * 16 + aColSel;
            uint32_t ah[4], al[4];
            ldsm_x4(ah, &s_xh[aRow][col]);
            ldsm_x4(al, &s_xl[aRow][col]);
            #pragma unroll
            for (int nt = 0; nt < 2; nt++) {
                mma_bf16(acc[nt], ah, bhf[nt][s]);
                mma_bf16(acc[nt], ah, blf[nt][s]);
                mma_bf16(acc[nt], al, bhf[nt][s]);
            }
        }

        int d0 = dsts[g], d1 = dsts[g + 8];
        #pragma unroll
        for (int nt = 0; nt < 2; nt++) {
            int col = wid * 16 + nt * 8 + tg * 2;
            if (d0 >= 0) {
                atomicAdd(&Y[(size_t)d0 * DD + col],     acc[nt][0]);
                atomicAdd(&Y[(size_t)d0 * DD + col + 1], acc[nt][1]);
            }
            if (d1 >= 0) {
                atomicAdd(&Y[(size_t)d1 * DD + col],     acc[nt][2]);
                atomicAdd(&Y[(size_t)d1 * DD + col + 1], acc[nt][3]);
            }
        }
    }
}

// ---------------- launcher (single stream) ----------------
extern "C" void kernel_launch(void* const* d_in, const int* in_sizes, int n_in,
                              void* d_out, int out_size) {
    const int*   entity = (const int*)d_in[0];
    const int*   eidx   = (const int*)d_in[1];
    const int*   etype  = (const int*)d_in[2];
    const float* emb    = (const float*)d_in[3];
    const float* basis1 = (const float*)d_in[4];
    const float* att1   = (const float*)d_in[5];
    const float* w1     = (const float*)d_in[6];
    const float* root1  = (const float*)d_in[7];
    const float* bias1  = (const float*)d_in[8];
    const float* basis2 = (const float*)d_in[9];
    const float* att2   = (const float*)d_in[10];
    const float* w2     = (const float*)d_in[11];
    const float* root2  = (const float*)d_in[12];
    const float* bias2  = (const float*)d_in[13];
    float* out = (float*)d_out;
    const int* src = eidx;
    const int* dst = eidx + EE;

    float *pX = nullptr, *pH = nullptr, *pW1 = nullptr, *pW2 = nullptr, *pD0 = nullptr, *pD1 = nullptr;
    cudaGetSymbolAddress((void**)&pX, g_X);
    cudaGetSymbolAddress((void**)&pH, g_H);
    cudaGetSymbolAddress((void**)&pW1, g_W1);
    cudaGetSymbolAddress((void**)&pW2, g_W2);
    cudaGetSymbolAddress((void**)&pD0, g_denom0);
    cudaGetSymbolAddress((void**)&pD1, g_denom1);

    cudaFuncSetAttribute(k_wbuild, cudaFuncAttributeMaxDynamicSharedMemorySize, WB_SMEM);

    const int NVEC = NN * DD / 4;
    const dim3 rootGrid(2, (NN + 63) / 64);

    k_gather_init<<<(NVEC + 255) / 256, 256>>>(entity, emb);
    k_hist<<<GB, GT>>>(etype);
    k_scan2<<<1, 512>>>();
    k_place<<<GB, GT>>>(etype);

    // ---- layer 1 ----
    k_wbuild<<<dim3(128, 8), 256, WB_SMEM>>>(att1, basis1, pW1, RR);
    k_alpha_exp<<<EE / 4, 128>>>(pX, src, dst, etype, w1, pD0, 0);
    k_root<<<rootGrid, 128>>>(pX, root1, bias1, pH, NN, 0);
    k_msg<<<RR, 256>>>(pX, pH, src, dst, pD0, 0, pW1);

    // ---- layer 2 (relu applied on read of H) ----
    k_wbuild<<<dim3(128, 8), 256, WB_SMEM>>>(att2, basis2, pW2, RR);
    k_alpha_exp<<<EE / 4, 128>>>(pH, src, dst, etype, w2, pD1, 1);
    k_root<<<rootGrid, 128>>>(pH, root2, bias2, out, NN, 1);
    k_msg<<<RR, 256>>>(pH, out, src, dst, pD1, 1, pW2);
}

// round 11
// speedup vs baseline: 1.0740x; 1.0317x over previous
#include <cuda_runtime.h>
#include <cuda_bf16.h>
#include <cstdint>

#define NN 20000
#define DD 128
#define EE 32768
#define RR 474
#define BB 64
#define GB 32
#define EPB (EE / GB)

// ---------------- device scratch ----------------
__device__ float g_X[NN * DD];
__device__ float g_H[NN * DD];
__device__ float g_W1[RR * DD * DD];
__device__ float g_W2[RR * DD * DD];
__device__ float g_alpha[EE];
__device__ float g_denom0[NN];
__device__ float g_denom1[NN];
__device__ int   g_bh[GB * RR];
__device__ int   g_offs[RR + 1];
__device__ int   g_order[EE];

// ---------------- mma / ldmatrix helpers ----------------
__device__ __forceinline__ void mma_bf16(float* d, const uint32_t* a, const uint32_t* b) {
    asm volatile(
        "mma.sync.aligned.m16n8k16.row.col.f32.bf16.bf16.f32 "
        "{%0,%1,%2,%3}, {%4,%5,%6,%7}, {%8,%9}, {%0,%1,%2,%3};"
        : "+f"(d[0]), "+f"(d[1]), "+f"(d[2]), "+f"(d[3])
        : "r"(a[0]), "r"(a[1]), "r"(a[2]), "r"(a[3]), "r"(b[0]), "r"(b[1]));
}
__device__ __forceinline__ void ldsm_x4(uint32_t* r, const void* p) {
    uint32_t addr = (uint32_t)__cvta_generic_to_shared(p);
    asm volatile("ldmatrix.sync.aligned.m8n8.x4.shared.b16 {%0,%1,%2,%3}, [%4];"
        : "=r"(r[0]), "=r"(r[1]), "=r"(r[2]), "=r"(r[3]) : "r"(addr));
}
__device__ __forceinline__ uint32_t pack2_bf16(float a, float b) {
    __nv_bfloat162 p = __floats2bfloat162_rn(a, b);
    return *reinterpret_cast<uint32_t*>(&p);
}
__device__ __forceinline__ void split_bf16(float v, __nv_bfloat16& h, float& lo) {
    h = __float2bfloat16(v);
    lo = v - __bfloat162float(h);
}

// ================= W build: C[M,16384] = A[M,64] @ B[64,16384] =================
#define WB_STRIDE 72
#define WB_A_HI 0
#define WB_A_LO (64 * WB_STRIDE * 2)
#define WB_B_HI (2 * 64 * WB_STRIDE * 2)
#define WB_B_LO (2 * 64 * WB_STRIDE * 2 + 128 * WB_STRIDE * 2)
#define WB_SMEM (2 * 64 * WB_STRIDE * 2 + 2 * 128 * WB_STRIDE * 2)  // 55296

__global__ void __launch_bounds__(256, 2)
k_wbuild(const float* __restrict__ A, const float* __restrict__ B,
         float* __restrict__ C, int M) {
    extern __shared__ char smem[];
    __nv_bfloat16* sAh = (__nv_bfloat16*)(smem + WB_A_HI);
    __nv_bfloat16* sAl = (__nv_bfloat16*)(smem + WB_A_LO);
    __nv_bfloat16* sBh = (__nv_bfloat16*)(smem + WB_B_HI);
    __nv_bfloat16* sBl = (__nv_bfloat16*)(smem + WB_B_LO);

    int t = threadIdx.x;
    int n0 = blockIdx.x * 128, m0 = blockIdx.y * 64;

    #pragma unroll
    for (int e = t; e < 64 * 64; e += 256) {
        int m = e >> 6, k = e & 63;
        float v = (m0 + m < M) ? A[(m0 + m) * 64 + k] : 0.f;
        __nv_bfloat16 h; float lo;
        split_bf16(v, h, lo);
        sAh[m * WB_STRIDE + k] = h;
        sAl[m * WB_STRIDE + k] = __float2bfloat16(lo);
    }
    #pragma unroll
    for (int e = t; e < 64 * 128; e += 256) {
        int k = e >> 7, n = e & 127;
        float v = B[(size_t)k * 16384 + n0 + n];
        __nv_bfloat16 h; float lo;
        split_bf16(v, h, lo);
        sBh[n * WB_STRIDE + k] = h;
        sBl[n * WB_STRIDE + k] = __float2bfloat16(lo);
    }
    __syncthreads();

    int wid = t >> 5, lane = t & 31;
    int warpM = wid >> 2, warpN = wid & 3;
    int g = lane >> 2, tg = lane & 3;

    int aRow = (lane & 15);
    int aColSel = ((lane >> 4) << 3);
    int bN = ((lane >> 4) << 3) + (lane & 7);
    int bKSel = (((lane >> 3) & 1) << 3);

    float acc[2][4][4];
    #pragma unroll
    for (int i = 0; i < 2; i++)
        #pragma unroll
        for (int j = 0; j < 4; j++)
            #pragma unroll
            for (int q = 0; q < 4; q++) acc[i][j][q] = 0.f;

    #pragma unroll
    for (int ks = 0; ks < 4; ks++) {
        int k0 = ks * 16;
        uint32_t ah[2][4], al[2][4];
        #pragma unroll
        for (int mt = 0; mt < 2; mt++) {
            int row = warpM * 32 + mt * 16 + aRow;
            ldsm_x4(ah[mt], &sAh[row * WB_STRIDE + k0 + aColSel]);
            ldsm_x4(al[mt], &sAl[row * WB_STRIDE + k0 + aColSel]);
        }
        uint32_t bh[4][2], bl[4][2];
        #pragma unroll
        for (int np = 0; np < 2; np++) {
            int n = warpN * 32 + np * 16 + bN;
            uint32_t tmp[4];
            ldsm_x4(tmp, &sBh[n * WB_STRIDE + k0 + bKSel]);
            bh[np * 2][0] = tmp[0]; bh[np * 2][1] = tmp[1];
            bh[np * 2 + 1][0] = tmp[2]; bh[np * 2 + 1][1] = tmp[3];
            ldsm_x4(tmp, &sBl[n * WB_STRIDE + k0 + bKSel]);
            bl[np * 2][0] = tmp[0]; bl[np * 2][1] = tmp[1];
            bl[np * 2 + 1][0] = tmp[2]; bl[np * 2 + 1][1] = tmp[3];
        }
        #pragma unroll
        for (int mt = 0; mt < 2; mt++)
            #pragma unroll
            for (int nt = 0; nt < 4; nt++) {
                mma_bf16(acc[mt][nt], ah[mt], bh[nt]);
                mma_bf16(acc[mt][nt], ah[mt], bl[nt]);
                mma_bf16(acc[mt][nt], al[mt], bh[nt]);
            }
    }

    #pragma unroll
    for (int mt = 0; mt < 2; mt++) {
        int r0 = m0 + warpM * 32 + mt * 16 + g;
        #pragma unroll
        for (int nt = 0; nt < 4; nt++) {
            int col = n0 + warpN * 32 + nt * 8 + tg * 2;
            if (r0 < M)
                *(float2*)&C[(size_t)r0 * 16384 + col] = make_float2(acc[mt][nt][0], acc[mt][nt][1]);
            if (r0 + 8 < M)
                *(float2*)&C[(size_t)(r0 + 8) * 16384 + col] = make_float2(acc[mt][nt][2], acc[mt][nt][3]);
        }
    }
}

// ================= root GEMM: C[M,128] = A[M,128] @ Broot + bias =================
#define RT_STRIDE 136
__global__ void __launch_bounds__(128, 4)
k_root(const float* __restrict__ A, const float* __restrict__ Broot,
       const float* __restrict__ bias, float* __restrict__ C, int M, int relu_in) {
    int n_base = blockIdx.x * 64;
    int m0 = blockIdx.y * 64;
    int t = threadIdx.x, wid = t >> 5, lane = t & 31;
    int g = lane >> 2, tg = lane & 3;

    uint32_t bhf[2][8][2], blf[2][8][2];
    #pragma unroll
    for (int nt = 0; nt < 2; nt++) {
        int n = n_base + wid * 16 + nt * 8 + g;
        #pragma unroll
        for (int s = 0; s < 8; s++) {
            int k0 = s * 16 + tg * 2;
            float w0 = Broot[(k0 + 0) * 128 + n];
            float w1 = Broot[(k0 + 1) * 128 + n];
            float w2 = Broot[(k0 + 8) * 128 + n];
            float w3 = Broot[(k0 + 9) * 128 + n];
            __nv_bfloat16 h0, h1, h2, h3; float l0, l1, l2, l3;
            split_bf16(w0, h0, l0); split_bf16(w1, h1, l1);
            split_bf16(w2, h2, l2); split_bf16(w3, h3, l3);
            bhf[nt][s][0] = pack2_bf16(__bfloat162float(h0), __bfloat162float(h1));
            bhf[nt][s][1] = pack2_bf16(__bfloat162float(h2), __bfloat162float(h3));
            blf[nt][s][0] = pack2_bf16(l0, l1);
            blf[nt][s][1] = pack2_bf16(l2, l3);
        }
    }

    __shared__ __align__(16) __nv_bfloat16 s_ah[64][RT_STRIDE];
    __shared__ __align__(16) __nv_bfloat16 s_al[64][RT_STRIDE];

    #pragma unroll
    for (int e = t; e < 64 * 128; e += 128) {
        int row = e >> 7, col = e & 127;
        float v = (m0 + row < M) ? A[(size_t)(m0 + row) * 128 + col] : 0.f;
        if (relu_in) v = fmaxf(v, 0.f);
        __nv_bfloat16 h; float lo;
        split_bf16(v, h, lo);
        s_ah[row][col] = h;
        s_al[row][col] = __float2bfloat16(lo);
    }
    __syncthreads();

    float2 biasv[2];
    #pragma unroll
    for (int nt = 0; nt < 2; nt++) {
        int col = n_base + wid * 16 + nt * 8 + tg * 2;
        biasv[nt] = make_float2(bias[col], bias[col + 1]);
    }

    int aRow = (lane & 15);
    int aColSel = ((lane >> 4) << 3);

    #pragma unroll
    for (int mt = 0; mt < 4; mt++) {
        float acc[2][4];
        #pragma unroll
        for (int nt = 0; nt < 2; nt++)
            #pragma unroll
            for (int q = 0; q < 4; q++) acc[nt][q] = 0.f;

        #pragma unroll
        for (int s = 0; s < 8; s++) {
            int row = mt * 16 + aRow;
            int col = s * 16 + aColSel;
            uint32_t ah[4], al[4];
            ldsm_x4(ah, &s_ah[row][col]);
            ldsm_x4(al, &s_al[row][col]);
            #pragma unroll
            for (int nt = 0; nt < 2; nt++) {
                mma_bf16(acc[nt], ah, bhf[nt][s]);
                mma_bf16(acc[nt], ah, blf[nt][s]);
                mma_bf16(acc[nt], al, bhf[nt][s]);
            }
        }

        int r0 = m0 + mt * 16 + g, r1 = r0 + 8;
        #pragma unroll
        for (int nt = 0; nt < 2; nt++) {
            int col = n_base + wid * 16 + nt * 8 + tg * 2;
            if (r0 < M)
                *(float2*)&C[(size_t)r0 * 128 + col] =
                    make_float2(acc[nt][0] + biasv[nt].x, acc[nt][1] + biasv[nt].y);
            if (r1 < M)
                *(float2*)&C[(size_t)r1 * 128 + col] =
                    make_float2(acc[nt][2] + biasv[nt].x, acc[nt][3] + biasv[nt].y);
        }
    }
}

// ---------------- gather + denom init + per-slice histogram ----------------
__global__ void k_gather_init(const int* __restrict__ entity, const float* __restrict__ emb,
                              const int* __restrict__ etype) {
    __shared__ int h[RR];
    int t = threadIdx.x, b = blockIdx.x;
    bool histBlock = (b < GB);
    if (histBlock) {
        for (int i = t; i < RR; i += 256) h[i] = 0;
        __syncthreads();
        int base = b * EPB;
        for (int i = t; i < EPB; i += 256) atomicAdd(&h[etype[base + i]], 1);
    }

    int g = b * 256 + t;
    if (g < NN) { g_denom0[g] = 0.f; g_denom1[g] = 0.f; }
    if (g < NN * DD / 4) {
        int elem = g * 4;
        int n = elem >> 7, d = elem & 127;
        int idx = entity[n];
        *(float4*)&g_X[elem] = *(const float4*)&emb[idx * DD + d];
    }

    if (histBlock) {
        __syncthreads();
        for (int i = t; i < RR; i += 256) g_bh[b * RR + i] = h[i];
    }
}

// ---------------- fused scan + place: each block redundantly scans, places its slice ----------------
__global__ void __launch_bounds__(512, 2)
k_scanplace(const int* __restrict__ etype) {
    __shared__ int tot[512];
    __shared__ int cur[RR];
    int t = threadIdx.x, b = blockIdx.x;

    // per-type: total over all slices + prefix over slices < b
    int sum = 0, pre = 0;
    if (t < RR) {
        #pragma unroll 8
        for (int bb = 0; bb < GB; bb++) {
            int c = g_bh[bb * RR + t];
            if (bb < b) pre += c;
            sum += c;
        }
    }
    tot[t] = (t < RR) ? sum : 0;
    __syncthreads();
    #pragma unroll
    for (int off = 1; off < 512; off <<= 1) {
        int v = (t >= off) ? tot[t - off] : 0;
        __syncthreads();
        tot[t] += v;
        __syncthreads();
    }
    if (t < RR) {
        cur[t] = (tot[t] - sum) + pre;   // exclusive type prefix + slice prefix
        if (b == 0) g_offs[t + 1] = tot[t];
    }
    if (b == 0 && t == 0) g_offs[0] = 0;
    __syncthreads();

    int base = b * EPB;
    for (int i = t; i < EPB; i += 512) {
        int e = base + i;
        int p = atomicAdd(&cur[etype[e]], 1);
        g_order[p] = e;
    }
}

// ---------------- fused logits+exp+denom ----------------
__global__ void k_alpha_exp(const float* __restrict__ X, const int* __restrict__ src,
                            const int* __restrict__ dst, const int* __restrict__ etype,
                            const float* __restrict__ wt, float* __restrict__ denom,
                            int relu_in) {
    int e = blockIdx.x * (blockDim.x >> 5) + (threadIdx.x >> 5);
    if (e >= EE) return;
    int lane = threadIdx.x & 31;
    int s = src[e], d = dst[e], r = etype[e];
    float4 xi = *(const float4*)&X[d * DD + lane * 4];
    float4 xj = *(const float4*)&X[s * DD + lane * 4];
    if (relu_in) {
        xi.x = fmaxf(xi.x, 0.f); xi.y = fmaxf(xi.y, 0.f);
        xi.z = fmaxf(xi.z, 0.f); xi.w = fmaxf(xi.w, 0.f);
        xj.x = fmaxf(xj.x, 0.f); xj.y = fmaxf(xj.y, 0.f);
        xj.z = fmaxf(xj.z, 0.f); xj.w = fmaxf(xj.w, 0.f);
    }
    float4 w  = *(const float4*)&wt[r * DD + lane * 4];
    float v = xi.x * w.x * xj.x + xi.y * w.y * xj.y + xi.z * w.z * xj.z + xi.w * w.w * xj.w;
    #pragma unroll
    for (int off = 16; off; off >>= 1) v += __shfl_xor_sync(0xffffffffu, v, off);
    if (lane == 0) {
        float a = expf(v);
        g_alpha[e] = a;
        atomicAdd(&denom[d], a);
    }
}

// ---------------- per-type messages on tensor cores ----------------
#define MSG_STRIDE 136
__global__ void __launch_bounds__(256, 2)
k_msg(const float* __restrict__ Xin, float* __restrict__ Y,
      const int* __restrict__ srcArr, const int* __restrict__ dstArr,
      const float* __restrict__ denom, int relu_in, const float* __restrict__ Wbuf) {
    int r = blockIdx.x;
    int base = g_offs[r];
    int cnt = g_offs[r + 1] - base;
    if (cnt == 0) return;
    int t = threadIdx.x, wid = t >> 5, lane = t & 31;
    int g = lane >> 2, tg = lane & 3;

    const float* Wr = Wbuf + (size_t)r * 16384;
    uint32_t bhf[2][8][2], blf[2][8][2];
    #pragma unroll
    for (int nt = 0; nt < 2; nt++) {
        int n = wid * 16 + nt * 8 + g;
        #pragma unroll
        for (int s = 0; s < 8; s++) {
            int k0 = s * 16 + tg * 2;
            float w0 = Wr[(k0 + 0) * 128 + n];
            float w1 = Wr[(k0 + 1) * 128 + n];
            float w2 = Wr[(k0 + 8) * 128 + n];
            float w3 = Wr[(k0 + 9) * 128 + n];
            __nv_bfloat16 h0, h1, h2, h3; float l0, l1, l2, l3;
            split_bf16(w0, h0, l0); split_bf16(w1, h1, l1);
            split_bf16(w2, h2, l2); split_bf16(w3, h3, l3);
            bhf[nt][s][0] = pack2_bf16(__bfloat162float(h0), __bfloat162float(h1));
            bhf[nt][s][1] = pack2_bf16(__bfloat162float(h2), __bfloat162float(h3));
            blf[nt][s][0] = pack2_bf16(l0, l1);
            blf[nt][s][1] = pack2_bf16(l2, l3);
        }
    }

    __shared__ __align__(16) __nv_bfloat16 s_xh[16][MSG_STRIDE];
    __shared__ __align__(16) __nv_bfloat16 s_xl[16][MSG_STRIDE];
    __shared__ int   dsts[16];
    __shared__ int   srcs[16];
    __shared__ float scl[16];

    int aRow = (lane & 15);
    int aColSel = ((lane >> 4) << 3);

    for (int g0 = 0; g0 < cnt; g0 += 16) {
        __syncthreads();
        if (t < 16) {
            int j = g0 + t;
            if (j < cnt) {
                int e = g_order[base + j];
                int d = dstArr[e];
                dsts[t] = d;
                srcs[t] = srcArr[e];
                scl[t]  = g_alpha[e] / denom[d];
            } else { dsts[t] = -1; srcs[t] = 0; scl[t] = 0.f; }
        }
        __syncthreads();
        #pragma unroll
        for (int j2 = 0; j2 < 16; j2 += 2) {
            int j = j2 + (t >> 7);
            int i = t & 127;
            float v = Xin[(size_t)srcs[j] * DD + i];
            if (relu_in) v = fmaxf(v, 0.f);
            v *= scl[j];
            __nv_bfloat16 h; float lo;
            split_bf16(v, h, lo);
            s_xh[j][i] = h;
            s_xl[j][i] = __float2bfloat16(lo);
        }
        __syncthreads();

        float acc[2][4];
        #pragma unroll
        for (int nt = 0; nt < 2; nt++)
            #pragma unroll
            for (int q = 0; q < 4; q++) acc[nt][q] = 0.f;

        #pragma unroll
        for (int s = 0; s < 8; s++) {
            int col = s * 16 + aColSel;
            uint32_t ah[4], al[4];
            ldsm_x4(ah, &s_xh[aRow][col]);
            ldsm_x4(al, &s_xl[aRow][col]);
            #pragma unroll
            for (int nt = 0; nt < 2; nt++) {
                mma_bf16(acc[nt], ah, bhf[nt][s]);
                mma_bf16(acc[nt], ah, blf[nt][s]);
                mma_bf16(acc[nt], al, bhf[nt][s]);
            }
        }

        int d0 = dsts[g], d1 = dsts[g + 8];
        #pragma unroll
        for (int nt = 0; nt < 2; nt++) {
            int col = wid * 16 + nt * 8 + tg * 2;
            if (d0 >= 0) {
                atomicAdd(&Y[(size_t)d0 * DD + col],     acc[nt][0]);
                atomicAdd(&Y[(size_t)d0 * DD + col + 1], acc[nt][1]);
            }
            if (d1 >= 0) {
                atomicAdd(&Y[(size_t)d1 * DD + col],     acc[nt][2]);
                atomicAdd(&Y[(size_t)d1 * DD + col + 1], acc[nt][3]);
            }
        }
    }
}

// ---------------- launcher (single stream, 10 launches) ----------------
extern "C" void kernel_launch(void* const* d_in, const int* in_sizes, int n_in,
                              void* d_out, int out_size) {
    const int*   entity = (const int*)d_in[0];
    const int*   eidx   = (const int*)d_in[1];
    const int*   etype  = (const int*)d_in[2];
    const float* emb    = (const float*)d_in[3];
    const float* basis1 = (const float*)d_in[4];
    const float* att1   = (const float*)d_in[5];
    const float* w1     = (const float*)d_in[6];
    const float* root1  = (const float*)d_in[7];
    const float* bias1  = (const float*)d_in[8];
    const float* basis2 = (const float*)d_in[9];
    const float* att2   = (const float*)d_in[10];
    const float* w2     = (const float*)d_in[11];
    const float* root2  = (const float*)d_in[12];
    const float* bias2  = (const float*)d_in[13];
    float* out = (float*)d_out;
    const int* src = eidx;
    const int* dst = eidx + EE;

    float *pX = nullptr, *pH = nullptr, *pW1 = nullptr, *pW2 = nullptr, *pD0 = nullptr, *pD1 = nullptr;
    cudaGetSymbolAddress((void**)&pX, g_X);
    cudaGetSymbolAddress((void**)&pH, g_H);
    cudaGetSymbolAddress((void**)&pW1, g_W1);
    cudaGetSymbolAddress((void**)&pW2, g_W2);
    cudaGetSymbolAddress((void**)&pD0, g_denom0);
    cudaGetSymbolAddress((void**)&pD1, g_denom1);

    cudaFuncSetAttribute(k_wbuild, cudaFuncAttributeMaxDynamicSharedMemorySize, WB_SMEM);

    const int NVEC = NN * DD / 4;
    const dim3 rootGrid(2, (NN + 63) / 64);

    k_gather_init<<<(NVEC + 255) / 256, 256>>>(entity, emb, etype);
    k_scanplace<<<GB, 512>>>(etype);

    // ---- layer 1 ----
    k_wbuild<<<dim3(128, 8), 256, WB_SMEM>>>(att1, basis1, pW1, RR);
    k_alpha_exp<<<EE / 4, 128>>>(pX, src, dst, etype, w1, pD0, 0);
    k_root<<<rootGrid, 128>>>(pX, root1, bias1, pH, NN, 0);
    k_msg<<<RR, 256>>>(pX, pH, src, dst, pD0, 0, pW1);

    // ---- layer 2 (relu applied on read of H) ----
    k_wbuild<<<dim3(128, 8), 256, WB_SMEM>>>(att2, basis2, pW2, RR);
    k_alpha_exp<<<EE / 4, 128>>>(pH, src, dst, etype, w2, pD1, 1);
    k_root<<<rootGrid, 128>>>(pH, root2, bias2, out, NN, 1);
    k_msg<<<RR, 256>>>(pH, out, src, dst, pD1, 1, pW2);
}

// round 13
// speedup vs baseline: 1.1232x; 1.0457x over previous
#include <cuda_runtime.h>
#include <cuda_bf16.h>
#include <cstdint>

#define NN 20000
#define DD 128
#define EE 32768
#define RR 474
#define BB 64
#define GB 32
#define EPB (EE / GB)

// ---------------- device scratch ----------------
__device__ float g_X[NN * DD];
__device__ float g_H[NN * DD];
__device__ float g_W1[RR * DD * DD];
__device__ float g_W2[RR * DD * DD];
__device__ float g_alpha[EE];
__device__ float g_denom0[NN];
__device__ float g_denom1[NN];
__device__ int   g_bh[GB * RR];
__device__ int   g_offs[RR + 1];
__device__ int   g_order[EE];

// ---------------- mma / ldmatrix helpers ----------------
__device__ __forceinline__ void mma_bf16(float* d, const uint32_t* a, const uint32_t* b) {
    asm volatile(
        "mma.sync.aligned.m16n8k16.row.col.f32.bf16.bf16.f32 "
        "{%0,%1,%2,%3}, {%4,%5,%6,%7}, {%8,%9}, {%0,%1,%2,%3};"
        : "+f"(d[0]), "+f"(d[1]), "+f"(d[2]), "+f"(d[3])
        : "r"(a[0]), "r"(a[1]), "r"(a[2]), "r"(a[3]), "r"(b[0]), "r"(b[1]));
}
__device__ __forceinline__ void ldsm_x4(uint32_t* r, const void* p) {
    uint32_t addr = (uint32_t)__cvta_generic_to_shared(p);
    asm volatile("ldmatrix.sync.aligned.m8n8.x4.shared.b16 {%0,%1,%2,%3}, [%4];"
        : "=r"(r[0]), "=r"(r[1]), "=r"(r[2]), "=r"(r[3]) : "r"(addr));
}
__device__ __forceinline__ uint32_t pack2_bf16(float a, float b) {
    __nv_bfloat162 p = __floats2bfloat162_rn(a, b);
    return *reinterpret_cast<uint32_t*>(&p);
}
__device__ __forceinline__ void split_bf16(float v, __nv_bfloat16& h, float& lo) {
    h = __float2bfloat16(v);
    lo = v - __bfloat162float(h);
}

// ================= W build: C[M,16384] = A[M,64] @ B[64,16384] =================
// grid (128 n, 2 m-groups); B staged ONCE per block, 4 m-tiles of 64 rows looped.
#define WB_STRIDE 72
#define WB_B_HI 0
#define WB_B_LO (128 * WB_STRIDE * 2)
#define WB_A_HI (2 * 128 * WB_STRIDE * 2)
#define WB_A_LO (2 * 128 * WB_STRIDE * 2 + 64 * WB_STRIDE * 2)
#define WB_SMEM (2 * 128 * WB_STRIDE * 2 + 2 * 64 * WB_STRIDE * 2)  // 55296

__global__ void __launch_bounds__(256, 2)
k_wbuild(const float* __restrict__ A, const float* __restrict__ B,
         float* __restrict__ C, int M) {
    extern __shared__ char smem[];
    __nv_bfloat16* sBh = (__nv_bfloat16*)(smem + WB_B_HI);
    __nv_bfloat16* sBl = (__nv_bfloat16*)(smem + WB_B_LO);
    __nv_bfloat16* sAh = (__nv_bfloat16*)(smem + WB_A_HI);
    __nv_bfloat16* sAl = (__nv_bfloat16*)(smem + WB_A_LO);

    int t = threadIdx.x;
    int n0 = blockIdx.x * 128;

    // stage B^T tile once
    #pragma unroll
    for (int e = t; e < 64 * 128; e += 256) {
        int k = e >> 7, n = e & 127;
        float v = B[(size_t)k * 16384 + n0 + n];
        __nv_bfloat16 h; float lo;
        split_bf16(v, h, lo);
        sBh[n * WB_STRIDE + k] = h;
        sBl[n * WB_STRIDE + k] = __float2bfloat16(lo);
    }

    int wid = t >> 5, lane = t & 31;
    int warpM = wid >> 2, warpN = wid & 3;
    int g = lane >> 2, tg = lane & 3;
    int aRow = (lane & 15);
    int aColSel = ((lane >> 4) << 3);
    int bN = ((lane >> 4) << 3) + (lane & 7);
    int bKSel = (((lane >> 3) & 1) << 3);

    for (int mt4 = 0; mt4 < 4; mt4++) {
        int m0 = blockIdx.y * 256 + mt4 * 64;
        __syncthreads();   // previous m-tile compute done with sA; first iter: B stage visible
        #pragma unroll
        for (int e = t; e < 64 * 64; e += 256) {
            int m = e >> 6, k = e & 63;
            float v = (m0 + m < M) ? A[(m0 + m) * 64 + k] : 0.f;
            __nv_bfloat16 h; float lo;
            split_bf16(v, h, lo);
            sAh[m * WB_STRIDE + k] = h;
            sAl[m * WB_STRIDE + k] = __float2bfloat16(lo);
        }
        __syncthreads();

        float acc[2][4][4];
        #pragma unroll
        for (int i = 0; i < 2; i++)
            #pragma unroll
            for (int j = 0; j < 4; j++)
                #pragma unroll
                for (int q = 0; q < 4; q++) acc[i][j][q] = 0.f;

        #pragma unroll
        for (int ks = 0; ks < 4; ks++) {
            int k0 = ks * 16;
            uint32_t ah[2][4], al[2][4];
            #pragma unroll
            for (int mt = 0; mt < 2; mt++) {
                int row = warpM * 32 + mt * 16 + aRow;
                ldsm_x4(ah[mt], &sAh[row * WB_STRIDE + k0 + aColSel]);
                ldsm_x4(al[mt], &sAl[row * WB_STRIDE + k0 + aColSel]);
            }
            uint32_t bh[4][2], bl[4][2];
            #pragma unroll
            for (int np = 0; np < 2; np++) {
                int n = warpN * 32 + np * 16 + bN;
                uint32_t tmp[4];
                ldsm_x4(tmp, &sBh[n * WB_STRIDE + k0 + bKSel]);
                bh[np * 2][0] = tmp[0]; bh[np * 2][1] = tmp[1];
                bh[np * 2 + 1][0] = tmp[2]; bh[np * 2 + 1][1] = tmp[3];
                ldsm_x4(tmp, &sBl[n * WB_STRIDE + k0 + bKSel]);
                bl[np * 2][0] = tmp[0]; bl[np * 2][1] = tmp[1];
                bl[np * 2 + 1][0] = tmp[2]; bl[np * 2 + 1][1] = tmp[3];
            }
            #pragma unroll
            for (int mt = 0; mt < 2; mt++)
                #pragma unroll
                for (int nt = 0; nt < 4; nt++) {
                    mma_bf16(acc[mt][nt], ah[mt], bh[nt]);
                    mma_bf16(acc[mt][nt], ah[mt], bl[nt]);
                    mma_bf16(acc[mt][nt], al[mt], bh[nt]);
                }
        }

        #pragma unroll
        for (int mt = 0; mt < 2; mt++) {
            int r0 = m0 + warpM * 32 + mt * 16 + g;
            #pragma unroll
            for (int nt = 0; nt < 4; nt++) {
                int col = n0 + warpN * 32 + nt * 8 + tg * 2;
                if (r0 < M)
                    *(float2*)&C[(size_t)r0 * 16384 + col] = make_float2(acc[mt][nt][0], acc[mt][nt][1]);
                if (r0 + 8 < M)
                    *(float2*)&C[(size_t)(r0 + 8) * 16384 + col] = make_float2(acc[mt][nt][2], acc[mt][nt][3]);
            }
        }
    }
}

// ================= root GEMM: C[M,128] = A[M,128] @ Broot + bias =================
#define RT_STRIDE 136
__global__ void __launch_bounds__(128, 4)
k_root(const float* __restrict__ A, const float* __restrict__ Broot,
       const float* __restrict__ bias, float* __restrict__ C, int M, int relu_in) {
    int n_base = blockIdx.x * 64;
    int m0 = blockIdx.y * 64;
    int t = threadIdx.x, wid = t >> 5, lane = t & 31;
    int g = lane >> 2, tg = lane & 3;

    uint32_t bhf[2][8][2], blf[2][8][2];
    #pragma unroll
    for (int nt = 0; nt < 2; nt++) {
        int n = n_base + wid * 16 + nt * 8 + g;
        #pragma unroll
        for (int s = 0; s < 8; s++) {
            int k0 = s * 16 + tg * 2;
            float w0 = Broot[(k0 + 0) * 128 + n];
            float w1 = Broot[(k0 + 1) * 128 + n];
            float w2 = Broot[(k0 + 8) * 128 + n];
            float w3 = Broot[(k0 + 9) * 128 + n];
            __nv_bfloat16 h0, h1, h2, h3; float l0, l1, l2, l3;
            split_bf16(w0, h0, l0); split_bf16(w1, h1, l1);
            split_bf16(w2, h2, l2); split_bf16(w3, h3, l3);
            bhf[nt][s][0] = pack2_bf16(__bfloat162float(h0), __bfloat162float(h1));
            bhf[nt][s][1] = pack2_bf16(__bfloat162float(h2), __bfloat162float(h3));
            blf[nt][s][0] = pack2_bf16(l0, l1);
            blf[nt][s][1] = pack2_bf16(l2, l3);
        }
    }

    __shared__ __align__(16) __nv_bfloat16 s_ah[64][RT_STRIDE];
    __shared__ __align__(16) __nv_bfloat16 s_al[64][RT_STRIDE];

    #pragma unroll
    for (int e = t; e < 64 * 128; e += 128) {
        int row = e >> 7, col = e & 127;
        float v = (m0 + row < M) ? A[(size_t)(m0 + row) * 128 + col] : 0.f;
        if (relu_in) v = fmaxf(v, 0.f);
        __nv_bfloat16 h; float lo;
        split_bf16(v, h, lo);
        s_ah[row][col] = h;
        s_al[row][col] = __float2bfloat16(lo);
    }
    __syncthreads();

    float2 biasv[2];
    #pragma unroll
    for (int nt = 0; nt < 2; nt++) {
        int col = n_base + wid * 16 + nt * 8 + tg * 2;
        biasv[nt] = make_float2(bias[col], bias[col + 1]);
    }

    int aRow = (lane & 15);
    int aColSel = ((lane >> 4) << 3);

    #pragma unroll
    for (int mt = 0; mt < 4; mt++) {
        float acc[2][4];
        #pragma unroll
        for (int nt = 0; nt < 2; nt++)
            #pragma unroll
            for (int q = 0; q < 4; q++) acc[nt][q] = 0.f;

        #pragma unroll
        for (int s = 0; s < 8; s++) {
            int row = mt * 16 + aRow;
            int col = s * 16 + aColSel;
            uint32_t ah[4], al[4];
            ldsm_x4(ah, &s_ah[row][col]);
            ldsm_x4(al, &s_al[row][col]);
            #pragma unroll
            for (int nt = 0; nt < 2; nt++) {
                mma_bf16(acc[nt], ah, bhf[nt][s]);
                mma_bf16(acc[nt], ah, blf[nt][s]);
                mma_bf16(acc[nt], al, bhf[nt][s]);
            }
        }

        int r0 = m0 + mt * 16 + g, r1 = r0 + 8;
        #pragma unroll
        for (int nt = 0; nt < 2; nt++) {
            int col = n_base + wid * 16 + nt * 8 + tg * 2;
            if (r0 < M)
                *(float2*)&C[(size_t)r0 * 128 + col] =
                    make_float2(acc[nt][0] + biasv[nt].x, acc[nt][1] + biasv[nt].y);
            if (r1 < M)
                *(float2*)&C[(size_t)r1 * 128 + col] =
                    make_float2(acc[nt][2] + biasv[nt].x, acc[nt][3] + biasv[nt].y);
        }
    }
}

// ---------------- gather + denom init + per-slice histogram ----------------
__global__ void k_gather_init(const int* __restrict__ entity, const float* __restrict__ emb,
                              const int* __restrict__ etype) {
    __shared__ int h[RR];
    int t = threadIdx.x, b = blockIdx.x;
    bool histBlock = (b < GB);
    if (histBlock) {
        for (int i = t; i < RR; i += 256) h[i] = 0;
        __syncthreads();
        int base = b * EPB;
        for (int i = t; i < EPB; i += 256) atomicAdd(&h[etype[base + i]], 1);
    }

    int g = b * 256 + t;
    if (g < NN) { g_denom0[g] = 0.f; g_denom1[g] = 0.f; }
    if (g < NN * DD / 4) {
        int elem = g * 4;
        int n = elem >> 7, d = elem & 127;
        int idx = entity[n];
        *(float4*)&g_X[elem] = *(const float4*)&emb[idx * DD + d];
    }

    if (histBlock) {
        __syncthreads();
        for (int i = t; i < RR; i += 256) g_bh[b * RR + i] = h[i];
    }
}

// ---------------- fused scan + place ----------------
__global__ void __launch_bounds__(512, 2)
k_scanplace(const int* __restrict__ etype) {
    __shared__ int tot[512];
    __shared__ int cur[RR];
    int t = threadIdx.x, b = blockIdx.x;

    int sum = 0, pre = 0;
    if (t < RR) {
        #pragma unroll 8
        for (int bb = 0; bb < GB; bb++) {
            int c = g_bh[bb * RR + t];
            if (bb < b) pre += c;
            sum += c;
        }
    }
    tot[t] = (t < RR) ? sum : 0;
    __syncthreads();
    #pragma unroll
    for (int off = 1; off < 512; off <<= 1) {
        int v = (t >= off) ? tot[t - off] : 0;
        __syncthreads();
        tot[t] += v;
        __syncthreads();
    }
    if (t < RR) {
        cur[t] = (tot[t] - sum) + pre;
        if (b == 0) g_offs[t + 1] = tot[t];
    }
    if (b == 0 && t == 0) g_offs[0] = 0;
    __syncthreads();

    int base = b * EPB;
    for (int i = t; i < EPB; i += 512) {
        int e = base + i;
        int p = atomicAdd(&cur[etype[e]], 1);
        g_order[p] = e;
    }
}

// ---------------- fused logits+exp+denom: 4 edges per warp, batched loads ----------------
__global__ void k_alpha_exp(const float* __restrict__ X, const int* __restrict__ src,
                            const int* __restrict__ dst, const int* __restrict__ etype,
                            const float* __restrict__ wt, float* __restrict__ denom,
                            int relu_in) {
    int warpId = (blockIdx.x * blockDim.x + threadIdx.x) >> 5;
    int e0 = warpId * 4;
    if (e0 >= EE) return;
    int lane = threadIdx.x & 31;

    int s[4], d[4], r[4];
    #pragma unroll
    for (int j = 0; j < 4; j++) {
        s[j] = src[e0 + j]; d[j] = dst[e0 + j]; r[j] = etype[e0 + j];
    }
    float4 xi[4], xj[4], w[4];
    #pragma unroll
    for (int j = 0; j < 4; j++) {
        xi[j] = *(const float4*)&X[(size_t)d[j] * DD + lane * 4];
        xj[j] = *(const float4*)&X[(size_t)s[j] * DD + lane * 4];
        w[j]  = *(const float4*)&wt[(size_t)r[j] * DD + lane * 4];
    }
    #pragma unroll
    for (int j = 0; j < 4; j++) {
        float4 a = xi[j], bq = xj[j];
        if (relu_in) {
            a.x = fmaxf(a.x, 0.f); a.y = fmaxf(a.y, 0.f);
            a.z = fmaxf(a.z, 0.f); a.w = fmaxf(a.w, 0.f);
            bq.x = fmaxf(bq.x, 0.f); bq.y = fmaxf(bq.y, 0.f);
            bq.z = fmaxf(bq.z, 0.f); bq.w = fmaxf(bq.w, 0.f);
        }
        float v = a.x * w[j].x * bq.x + a.y * w[j].y * bq.y
                + a.z * w[j].z * bq.z + a.w * w[j].w * bq.w;
        #pragma unroll
        for (int off = 16; off; off >>= 1) v += __shfl_xor_sync(0xffffffffu, v, off);
        if (lane == 0) {
            float e = expf(v);
            g_alpha[e0 + j] = e;
            atomicAdd(&denom[d[j]], e);
        }
    }
}

// ---------------- per-type messages on tensor cores ----------------
#define MSG_STRIDE 136
__global__ void __launch_bounds__(256, 2)
k_msg(const float* __restrict__ Xin, float* __restrict__ Y,
      const int* __restrict__ srcArr, const int* __restrict__ dstArr,
      const float* __restrict__ denom, int relu_in, const float* __restrict__ Wbuf) {
    int r = blockIdx.x;
    int base = g_offs[r];
    int cnt = g_offs[r + 1] - base;
    if (cnt == 0) return;
    int t = threadIdx.x, wid = t >> 5, lane = t & 31;
    int g = lane >> 2, tg = lane & 3;

    const float* Wr = Wbuf + (size_t)r * 16384;
    uint32_t bhf[2][8][2], blf[2][8][2];
    #pragma unroll
    for (int nt = 0; nt < 2; nt++) {
        int n = wid * 16 + nt * 8 + g;
        #pragma unroll
        for (int s = 0; s < 8; s++) {
            int k0 = s * 16 + tg * 2;
            float w0 = Wr[(k0 + 0) * 128 + n];
            float w1 = Wr[(k0 + 1) * 128 + n];
            float w2 = Wr[(k0 + 8) * 128 + n];
            float w3 = Wr[(k0 + 9) * 128 + n];
            __nv_bfloat16 h0, h1, h2, h3; float l0, l1, l2, l3;
            split_bf16(w0, h0, l0); split_bf16(w1, h1, l1);
            split_bf16(w2, h2, l2); split_bf16(w3, h3, l3);
            bhf[nt][s][0] = pack2_bf16(__bfloat162float(h0), __bfloat162float(h1));
            bhf[nt][s][1] = pack2_bf16(__bfloat162float(h2), __bfloat162float(h3));
            blf[nt][s][0] = pack2_bf16(l0, l1);
            blf[nt][s][1] = pack2_bf16(l2, l3);
        }
    }

    __shared__ __align__(16) __nv_bfloat16 s_xh[16][MSG_STRIDE];
    __shared__ __align__(16) __nv_bfloat16 s_xl[16][MSG_STRIDE];
    __shared__ int   dsts[16];
    __shared__ int   srcs[16];
    __shared__ float scl[16];

    int aRow = (lane & 15);
    int aColSel = ((lane >> 4) << 3);

    for (int g0 = 0; g0 < cnt; g0 += 16) {
        __syncthreads();
        if (t < 16) {
            int j = g0 + t;
            if (j < cnt) {
                int e = g_order[base + j];
                int d = dstArr[e];
                dsts[t] = d;
                srcs[t] = srcArr[e];
                scl[t]  = g_alpha[e] / denom[d];
            } else { dsts[t] = -1; srcs[t] = 0; scl[t] = 0.f; }
        }
        __syncthreads();
        #pragma unroll
        for (int j2 = 0; j2 < 16; j2 += 2) {
            int j = j2 + (t >> 7);
            int i = t & 127;
            float v = Xin[(size_t)srcs[j] * DD + i];
            if (relu_in) v = fmaxf(v, 0.f);
            v *= scl[j];
            __nv_bfloat16 h; float lo;
            split_bf16(v, h, lo);
            s_xh[j][i] = h;
            s_xl[j][i] = __float2bfloat16(lo);
        }
        __syncthreads();

        float acc[2][4];
        #pragma unroll
        for (int nt = 0; nt < 2; nt++)
            #pragma unroll
            for (int q = 0; q < 4; q++) acc[nt][q] = 0.f;

        #pragma unroll
        for (int s = 0; s < 8; s++) {
            int col = s * 16 + aColSel;
            uint32_t ah[4], al[4];
            ldsm_x4(ah, &s_xh[aRow][col]);
            ldsm_x4(al, &s_xl[aRow][col]);
            #pragma unroll
            for (int nt = 0; nt < 2; nt++) {
                mma_bf16(acc[nt], ah, bhf[nt][s]);
                mma_bf16(acc[nt], ah, blf[nt][s]);
                mma_bf16(acc[nt], al, bhf[nt][s]);
            }
        }

        int d0 = dsts[g], d1 = dsts[g + 8];
        #pragma unroll
        for (int nt = 0; nt < 2; nt++) {
            int col = wid * 16 + nt * 8 + tg * 2;
            if (d0 >= 0) {
                atomicAdd(&Y[(size_t)d0 * DD + col],     acc[nt][0]);
                atomicAdd(&Y[(size_t)d0 * DD + col + 1], acc[nt][1]);
            }
            if (d1 >= 0) {
                atomicAdd(&Y[(size_t)d1 * DD + col],     acc[nt][2]);
                atomicAdd(&Y[(size_t)d1 * DD + col + 1], acc[nt][3]);
            }
        }
    }
}

// ---------------- launcher (single stream, 10 launches) ----------------
extern "C" void kernel_launch(void* const* d_in, const int* in_sizes, int n_in,
                              void* d_out, int out_size) {
    const int*   entity = (const int*)d_in[0];
    const int*   eidx   = (const int*)d_in[1];
    const int*   etype  = (const int*)d_in[2];
    const float* emb    = (const float*)d_in[3];
    const float* basis1 = (const float*)d_in[4];
    const float* att1   = (const float*)d_in[5];
    const float* w1     = (const float*)d_in[6];
    const float* root1  = (const float*)d_in[7];
    const float* bias1  = (const float*)d_in[8];
    const float* basis2 = (const float*)d_in[9];
    const float* att2   = (const float*)d_in[10];
    const float* w2     = (const float*)d_in[11];
    const float* root2  = (const float*)d_in[12];
    const float* bias2  = (const float*)d_in[13];
    float* out = (float*)d_out;
    const int* src = eidx;
    const int* dst = eidx + EE;

    float *pX = nullptr, *pH = nullptr, *pW1 = nullptr, *pW2 = nullptr, *pD0 = nullptr, *pD1 = nullptr;
    cudaGetSymbolAddress((void**)&pX, g_X);
    cudaGetSymbolAddress((void**)&pH, g_H);
    cudaGetSymbolAddress((void**)&pW1, g_W1);
    cudaGetSymbolAddress((void**)&pW2, g_W2);
    cudaGetSymbolAddress((void**)&pD0, g_denom0);
    cudaGetSymbolAddress((void**)&pD1, g_denom1);

    cudaFuncSetAttribute(k_wbuild, cudaFuncAttributeMaxDynamicSharedMemorySize, WB_SMEM);

    const int NVEC = NN * DD / 4;
    const dim3 rootGrid(2, (NN + 63) / 64);
    const int ALPHA_BLOCKS = EE / 4 / 8;   // 4 edges/warp, 8 warps/block -> 1024 blocks

    k_gather_init<<<(NVEC + 255) / 256, 256>>>(entity, emb, etype);
    k_scanplace<<<GB, 512>>>(etype);

    // ---- layer 1 ----
    k_wbuild<<<dim3(128, 2), 256, WB_SMEM>>>(att1, basis1, pW1, RR);
    k_alpha_exp<<<ALPHA_BLOCKS, 256>>>(pX, src, dst, etype, w1, pD0, 0);
    k_root<<<rootGrid, 128>>>(pX, root1, bias1, pH, NN, 0);
    k_msg<<<RR, 256>>>(pX, pH, src, dst, pD0, 0, pW1);

    // ---- layer 2 (relu applied on read of H) ----
    k_wbuild<<<dim3(128, 2), 256, WB_SMEM>>>(att2, basis2, pW2, RR);
    k_alpha_exp<<<ALPHA_BLOCKS, 256>>>(pH, src, dst, etype, w2, pD1, 1);
    k_root<<<rootGrid, 128>>>(pH, root2, bias2, out, NN, 1);
    k_msg<<<RR, 256>>>(pH, out, src, dst, pD1, 1, pW2);
}

// round 14
// speedup vs baseline: 1.3094x; 1.1658x over previous
#include <cuda_runtime.h>
#include <cuda_bf16.h>
#include <cstdint>

#define NN 20000
#define DD 128
#define EE 32768
#define RR 474
#define BB 64
#define GB 32
#define EPB (EE / GB)

// ---------------- device scratch ----------------
__device__ float g_X[NN * DD];
__device__ float g_H[NN * DD];
__device__ float g_W1[RR * DD * DD];
__device__ float g_W2[RR * DD * DD];
__device__ float g_alpha[EE];
__device__ float g_denom0[NN];
__device__ float g_denom1[NN];
__device__ int   g_bh[GB * RR];
__device__ int   g_offs[RR + 1];
__device__ int   g_order[EE];
__device__ int   g_esrc[EE];      // sorted-order src
__device__ int   g_edst[EE];      // sorted-order dst
__device__ float g_escl[EE];      // sorted-order alpha/denom (per layer, rebuilt)

// ---------------- mma / ldmatrix helpers ----------------
__device__ __forceinline__ void mma_bf16(float* d, const uint32_t* a, const uint32_t* b) {
    asm volatile(
        "mma.sync.aligned.m16n8k16.row.col.f32.bf16.bf16.f32 "
        "{%0,%1,%2,%3}, {%4,%5,%6,%7}, {%8,%9}, {%0,%1,%2,%3};"
        : "+f"(d[0]), "+f"(d[1]), "+f"(d[2]), "+f"(d[3])
        : "r"(a[0]), "r"(a[1]), "r"(a[2]), "r"(a[3]), "r"(b[0]), "r"(b[1]));
}
__device__ __forceinline__ void ldsm_x4(uint32_t* r, const void* p) {
    uint32_t addr = (uint32_t)__cvta_generic_to_shared(p);
    asm volatile("ldmatrix.sync.aligned.m8n8.x4.shared.b16 {%0,%1,%2,%3}, [%4];"
        : "=r"(r[0]), "=r"(r[1]), "=r"(r[2]), "=r"(r[3]) : "r"(addr));
}
__device__ __forceinline__ uint32_t pack2_bf16(float a, float b) {
    __nv_bfloat162 p = __floats2bfloat162_rn(a, b);
    return *reinterpret_cast<uint32_t*>(&p);
}
__device__ __forceinline__ void split_bf16(float v, __nv_bfloat16& h, float& lo) {
    h = __float2bfloat16(v);
    lo = v - __bfloat162float(h);
}

// ================= W build: C[M,16384] = A[M,64] @ B[64,16384] =================
#define WB_STRIDE 72
#define WB_B_HI 0
#define WB_B_LO (128 * WB_STRIDE * 2)
#define WB_A_HI (2 * 128 * WB_STRIDE * 2)
#define WB_A_LO (2 * 128 * WB_STRIDE * 2 + 64 * WB_STRIDE * 2)
#define WB_SMEM (2 * 128 * WB_STRIDE * 2 + 2 * 64 * WB_STRIDE * 2)  // 55296

__global__ void __launch_bounds__(256, 2)
k_wbuild(const float* __restrict__ A, const float* __restrict__ B,
         float* __restrict__ C, int M) {
    extern __shared__ char smem[];
    __nv_bfloat16* sBh = (__nv_bfloat16*)(smem + WB_B_HI);
    __nv_bfloat16* sBl = (__nv_bfloat16*)(smem + WB_B_LO);
    __nv_bfloat16* sAh = (__nv_bfloat16*)(smem + WB_A_HI);
    __nv_bfloat16* sAl = (__nv_bfloat16*)(smem + WB_A_LO);

    int t = threadIdx.x;
    int n0 = blockIdx.x * 128;

    #pragma unroll
    for (int e = t; e < 64 * 128; e += 256) {
        int k = e >> 7, n = e & 127;
        float v = B[(size_t)k * 16384 + n0 + n];
        __nv_bfloat16 h; float lo;
        split_bf16(v, h, lo);
        sBh[n * WB_STRIDE + k] = h;
        sBl[n * WB_STRIDE + k] = __float2bfloat16(lo);
    }

    int wid = t >> 5, lane = t & 31;
    int warpM = wid >> 2, warpN = wid & 3;
    int g = lane >> 2, tg = lane & 3;
    int aRow = (lane & 15);
    int aColSel = ((lane >> 4) << 3);
    int bN = ((lane >> 4) << 3) + (lane & 7);
    int bKSel = (((lane >> 3) & 1) << 3);

    for (int mt4 = 0; mt4 < 4; mt4++) {
        int m0 = blockIdx.y * 256 + mt4 * 64;
        __syncthreads();
        #pragma unroll
        for (int e = t; e < 64 * 64; e += 256) {
            int m = e >> 6, k = e & 63;
            float v = (m0 + m < M) ? A[(m0 + m) * 64 + k] : 0.f;
            __nv_bfloat16 h; float lo;
            split_bf16(v, h, lo);
            sAh[m * WB_STRIDE + k] = h;
            sAl[m * WB_STRIDE + k] = __float2bfloat16(lo);
        }
        __syncthreads();

        float acc[2][4][4];
        #pragma unroll
        for (int i = 0; i < 2; i++)
            #pragma unroll
            for (int j = 0; j < 4; j++)
                #pragma unroll
                for (int q = 0; q < 4; q++) acc[i][j][q] = 0.f;

        #pragma unroll
        for (int ks = 0; ks < 4; ks++) {
            int k0 = ks * 16;
            uint32_t ah[2][4], al[2][4];
            #pragma unroll
            for (int mt = 0; mt < 2; mt++) {
                int row = warpM * 32 + mt * 16 + aRow;
                ldsm_x4(ah[mt], &sAh[row * WB_STRIDE + k0 + aColSel]);
                ldsm_x4(al[mt], &sAl[row * WB_STRIDE + k0 + aColSel]);
            }
            uint32_t bh[4][2], bl[4][2];
            #pragma unroll
            for (int np = 0; np < 2; np++) {
                int n = warpN * 32 + np * 16 + bN;
                uint32_t tmp[4];
                ldsm_x4(tmp, &sBh[n * WB_STRIDE + k0 + bKSel]);
                bh[np * 2][0] = tmp[0]; bh[np * 2][1] = tmp[1];
                bh[np * 2 + 1][0] = tmp[2]; bh[np * 2 + 1][1] = tmp[3];
                ldsm_x4(tmp, &sBl[n * WB_STRIDE + k0 + bKSel]);
                bl[np * 2][0] = tmp[0]; bl[np * 2][1] = tmp[1];
                bl[np * 2 + 1][0] = tmp[2]; bl[np * 2 + 1][1] = tmp[3];
            }
            #pragma unroll
            for (int mt = 0; mt < 2; mt++)
                #pragma unroll
                for (int nt = 0; nt < 4; nt++) {
                    mma_bf16(acc[mt][nt], ah[mt], bh[nt]);
                    mma_bf16(acc[mt][nt], ah[mt], bl[nt]);
                    mma_bf16(acc[mt][nt], al[mt], bh[nt]);
                }
        }

        #pragma unroll
        for (int mt = 0; mt < 2; mt++) {
            int r0 = m0 + warpM * 32 + mt * 16 + g;
            #pragma unroll
            for (int nt = 0; nt < 4; nt++) {
                int col = n0 + warpN * 32 + nt * 8 + tg * 2;
                if (r0 < M)
                    *(float2*)&C[(size_t)r0 * 16384 + col] = make_float2(acc[mt][nt][0], acc[mt][nt][1]);
                if (r0 + 8 < M)
                    *(float2*)&C[(size_t)(r0 + 8) * 16384 + col] = make_float2(acc[mt][nt][2], acc[mt][nt][3]);
            }
        }
    }
}

// ================= root GEMM + fused per-edge scale precompute =================
// grid (3, 313): x<2 = GEMM halves; x==2 = scl prep (runs after alpha, denom ready).
#define RT_STRIDE 136
__global__ void __launch_bounds__(128, 4)
k_root(const float* __restrict__ A, const float* __restrict__ Broot,
       const float* __restrict__ bias, float* __restrict__ C, int M, int relu_in,
       const float* __restrict__ denom) {
    int t = threadIdx.x;

    if (blockIdx.x == 2) {
        // prep: g_escl[j] = alpha[order[j]] / denom[edst[j]]   (sorted order)
        int j = blockIdx.y * 128 + t;
        if (j < EE) {
            int e = g_order[j];
            g_escl[j] = g_alpha[e] / denom[g_edst[j]];
        }
        return;
    }

    int n_base = blockIdx.x * 64;
    int m0 = blockIdx.y * 64;
    int wid = t >> 5, lane = t & 31;
    int g = lane >> 2, tg = lane & 3;

    uint32_t bhf[2][8][2], blf[2][8][2];
    #pragma unroll
    for (int nt = 0; nt < 2; nt++) {
        int n = n_base + wid * 16 + nt * 8 + g;
        #pragma unroll
        for (int s = 0; s < 8; s++) {
            int k0 = s * 16 + tg * 2;
            float w0 = Broot[(k0 + 0) * 128 + n];
            float w1 = Broot[(k0 + 1) * 128 + n];
            float w2 = Broot[(k0 + 8) * 128 + n];
            float w3 = Broot[(k0 + 9) * 128 + n];
            __nv_bfloat16 h0, h1, h2, h3; float l0, l1, l2, l3;
            split_bf16(w0, h0, l0); split_bf16(w1, h1, l1);
            split_bf16(w2, h2, l2); split_bf16(w3, h3, l3);
            bhf[nt][s][0] = pack2_bf16(__bfloat162float(h0), __bfloat162float(h1));
            bhf[nt][s][1] = pack2_bf16(__bfloat162float(h2), __bfloat162float(h3));
            blf[nt][s][0] = pack2_bf16(l0, l1);
            blf[nt][s][1] = pack2_bf16(l2, l3);
        }
    }

    __shared__ __align__(16) __nv_bfloat16 s_ah[64][RT_STRIDE];
    __shared__ __align__(16) __nv_bfloat16 s_al[64][RT_STRIDE];

    #pragma unroll
    for (int e = t; e < 64 * 128; e += 128) {
        int row = e >> 7, col = e & 127;
        float v = (m0 + row < M) ? A[(size_t)(m0 + row) * 128 + col] : 0.f;
        if (relu_in) v = fmaxf(v, 0.f);
        __nv_bfloat16 h; float lo;
        split_bf16(v, h, lo);
        s_ah[row][col] = h;
        s_al[row][col] = __float2bfloat16(lo);
    }
    __syncthreads();

    float2 biasv[2];
    #pragma unroll
    for (int nt = 0; nt < 2; nt++) {
        int col = n_base + wid * 16 + nt * 8 + tg * 2;
        biasv[nt] = make_float2(bias[col], bias[col + 1]);
    }

    int aRow = (lane & 15);
    int aColSel = ((lane >> 4) << 3);

    #pragma unroll
    for (int mt = 0; mt < 4; mt++) {
        float acc[2][4];
        #pragma unroll
        for (int nt = 0; nt < 2; nt++)
            #pragma unroll
            for (int q = 0; q < 4; q++) acc[nt][q] = 0.f;

        #pragma unroll
        for (int s = 0; s < 8; s++) {
            int row = mt * 16 + aRow;
            int col = s * 16 + aColSel;
            uint32_t ah[4], al[4];
            ldsm_x4(ah, &s_ah[row][col]);
            ldsm_x4(al, &s_al[row][col]);
            #pragma unroll
            for (int nt = 0; nt < 2; nt++) {
                mma_bf16(acc[nt], ah, bhf[nt][s]);
                mma_bf16(acc[nt], ah, blf[nt][s]);
                mma_bf16(acc[nt], al, bhf[nt][s]);
            }
        }

        int r0 = m0 + mt * 16 + g, r1 = r0 + 8;
        #pragma unroll
        for (int nt = 0; nt < 2; nt++) {
            int col = n_base + wid * 16 + nt * 8 + tg * 2;
            if (r0 < M)
                *(float2*)&C[(size_t)r0 * 128 + col] =
                    make_float2(acc[nt][0] + biasv[nt].x, acc[nt][1] + biasv[nt].y);
            if (r1 < M)
                *(float2*)&C[(size_t)r1 * 128 + col] =
                    make_float2(acc[nt][2] + biasv[nt].x, acc[nt][3] + biasv[nt].y);
        }
    }
}

// ---------------- gather + denom init + per-slice histogram ----------------
__global__ void k_gather_init(const int* __restrict__ entity, const float* __restrict__ emb,
                              const int* __restrict__ etype) {
    __shared__ int h[RR];
    int t = threadIdx.x, b = blockIdx.x;
    bool histBlock = (b < GB);
    if (histBlock) {
        for (int i = t; i < RR; i += 256) h[i] = 0;
        __syncthreads();
        int base = b * EPB;
        for (int i = t; i < EPB; i += 256) atomicAdd(&h[etype[base + i]], 1);
    }

    int g = b * 256 + t;
    if (g < NN) { g_denom0[g] = 0.f; g_denom1[g] = 0.f; }
    if (g < NN * DD / 4) {
        int elem = g * 4;
        int n = elem >> 7, d = elem & 127;
        int idx = entity[n];
        *(float4*)&g_X[elem] = *(const float4*)&emb[idx * DD + d];
    }

    if (histBlock) {
        __syncthreads();
        for (int i = t; i < RR; i += 256) g_bh[b * RR + i] = h[i];
    }
}

// ---------------- fused scan + place (also writes sorted src/dst) ----------------
__global__ void __launch_bounds__(512, 2)
k_scanplace(const int* __restrict__ etype, const int* __restrict__ src,
            const int* __restrict__ dst) {
    __shared__ int tot[512];
    __shared__ int cur[RR];
    int t = threadIdx.x, b = blockIdx.x;

    int sum = 0, pre = 0;
    if (t < RR) {
        #pragma unroll 8
        for (int bb = 0; bb < GB; bb++) {
            int c = g_bh[bb * RR + t];
            if (bb < b) pre += c;
            sum += c;
        }
    }
    tot[t] = (t < RR) ? sum : 0;
    __syncthreads();
    #pragma unroll
    for (int off = 1; off < 512; off <<= 1) {
        int v = (t >= off) ? tot[t - off] : 0;
        __syncthreads();
        tot[t] += v;
        __syncthreads();
    }
    if (t < RR) {
        cur[t] = (tot[t] - sum) + pre;
        if (b == 0) g_offs[t + 1] = tot[t];
    }
    if (b == 0 && t == 0) g_offs[0] = 0;
    __syncthreads();

    int base = b * EPB;
    for (int i = t; i < EPB; i += 512) {
        int e = base + i;
        int p = atomicAdd(&cur[etype[e]], 1);
        g_order[p] = e;
        g_esrc[p] = src[e];
        g_edst[p] = dst[e];
    }
}

// ---------------- fused logits+exp+denom: 4 edges per warp ----------------
__global__ void k_alpha_exp(const float* __restrict__ X, const int* __restrict__ src,
                            const int* __restrict__ dst, const int* __restrict__ etype,
                            const float* __restrict__ wt, float* __restrict__ denom,
                            int relu_in) {
    int warpId = (blockIdx.x * blockDim.x + threadIdx.x) >> 5;
    int e0 = warpId * 4;
    if (e0 >= EE) return;
    int lane = threadIdx.x & 31;

    int s[4], d[4], r[4];
    #pragma unroll
    for (int j = 0; j < 4; j++) {
        s[j] = src[e0 + j]; d[j] = dst[e0 + j]; r[j] = etype[e0 + j];
    }
    float4 xi[4], xj[4], w[4];
    #pragma unroll
    for (int j = 0; j < 4; j++) {
        xi[j] = *(const float4*)&X[(size_t)d[j] * DD + lane * 4];
        xj[j] = *(const float4*)&X[(size_t)s[j] * DD + lane * 4];
        w[j]  = *(const float4*)&wt[(size_t)r[j] * DD + lane * 4];
    }
    #pragma unroll
    for (int j = 0; j < 4; j++) {
        float4 a = xi[j], bq = xj[j];
        if (relu_in) {
            a.x = fmaxf(a.x, 0.f); a.y = fmaxf(a.y, 0.f);
            a.z = fmaxf(a.z, 0.f); a.w = fmaxf(a.w, 0.f);
            bq.x = fmaxf(bq.x, 0.f); bq.y = fmaxf(bq.y, 0.f);
            bq.z = fmaxf(bq.z, 0.f); bq.w = fmaxf(bq.w, 0.f);
        }
        float v = a.x * w[j].x * bq.x + a.y * w[j].y * bq.y
                + a.z * w[j].z * bq.z + a.w * w[j].w * bq.w;
        #pragma unroll
        for (int off = 16; off; off >>= 1) v += __shfl_xor_sync(0xffffffffu, v, off);
        if (lane == 0) {
            float e = expf(v);
            g_alpha[e0 + j] = e;
            atomicAdd(&denom[d[j]], e);
        }
    }
}

// ---------------- per-type messages on tensor cores ----------------
#define MSG_STRIDE 136
__global__ void __launch_bounds__(256, 2)
k_msg(const float* __restrict__ Xin, float* __restrict__ Y,
      int relu_in, const float* __restrict__ Wbuf) {
    int r = blockIdx.x;
    int base = g_offs[r];
    int cnt = g_offs[r + 1] - base;
    if (cnt == 0) return;
    int t = threadIdx.x, wid = t >> 5, lane = t & 31;
    int g = lane >> 2, tg = lane & 3;

    const float* Wr = Wbuf + (size_t)r * 16384;
    uint32_t bhf[2][8][2], blf[2][8][2];
    #pragma unroll
    for (int nt = 0; nt < 2; nt++) {
        int n = wid * 16 + nt * 8 + g;
        #pragma unroll
        for (int s = 0; s < 8; s++) {
            int k0 = s * 16 + tg * 2;
            float w0 = Wr[(k0 + 0) * 128 + n];
            float w1 = Wr[(k0 + 1) * 128 + n];
            float w2 = Wr[(k0 + 8) * 128 + n];
            float w3 = Wr[(k0 + 9) * 128 + n];
            __nv_bfloat16 h0, h1, h2, h3; float l0, l1, l2, l3;
            split_bf16(w0, h0, l0); split_bf16(w1, h1, l1);
            split_bf16(w2, h2, l2); split_bf16(w3, h3, l3);
            bhf[nt][s][0] = pack2_bf16(__bfloat162float(h0), __bfloat162float(h1));
            bhf[nt][s][1] = pack2_bf16(__bfloat162float(h2), __bfloat162float(h3));
            blf[nt][s][0] = pack2_bf16(l0, l1);
            blf[nt][s][1] = pack2_bf16(l2, l3);
        }
    }

    __shared__ __align__(16) __nv_bfloat16 s_xh[16][MSG_STRIDE];
    __shared__ __align__(16) __nv_bfloat16 s_xl[16][MSG_STRIDE];
    __shared__ int   dsts[16];
    __shared__ int   srcs[16];
    __shared__ float scl[16];

    int aRow = (lane & 15);
    int aColSel = ((lane >> 4) << 3);

    for (int g0 = 0; g0 < cnt; g0 += 16) {
        __syncthreads();
        if (t < 16) {
            int j = g0 + t;
            if (j < cnt) {
                dsts[t] = g_edst[base + j];
                srcs[t] = g_esrc[base + j];
                scl[t]  = g_escl[base + j];
            } else { dsts[t] = -1; srcs[t] = 0; scl[t] = 0.f; }
        }
        __syncthreads();
        // stage 16 x 128: 4 rows per pass, float2 loads + packed uint32 STS
        #pragma unroll
        for (int j4 = 0; j4 < 16; j4 += 4) {
            int j = j4 + (t >> 6);
            int i = (t & 63) * 2;
            float2 v = *(const float2*)&Xin[(size_t)srcs[j] * DD + i];
            if (relu_in) { v.x = fmaxf(v.x, 0.f); v.y = fmaxf(v.y, 0.f); }
            float sc = scl[j];
            v.x *= sc; v.y *= sc;
            __nv_bfloat16 h0, h1; float l0, l1;
            split_bf16(v.x, h0, l0);
            split_bf16(v.y, h1, l1);
            *(uint32_t*)&s_xh[j][i] = pack2_bf16(__bfloat162float(h0), __bfloat162float(h1));
            *(uint32_t*)&s_xl[j][i] = pack2_bf16(l0, l1);
        }
        __syncthreads();

        float acc[2][4];
        #pragma unroll
        for (int nt = 0; nt < 2; nt++)
            #pragma unroll
            for (int q = 0; q < 4; q++) acc[nt][q] = 0.f;

        #pragma unroll
        for (int s = 0; s < 8; s++) {
            int col = s * 16 + aColSel;
            uint32_t ah[4], al[4];
            ldsm_x4(ah, &s_xh[aRow][col]);
            ldsm_x4(al, &s_xl[aRow][col]);
            #pragma unroll
            for (int nt = 0; nt < 2; nt++) {
                mma_bf16(acc[nt], ah, bhf[nt][s]);
                mma_bf16(acc[nt], ah, blf[nt][s]);
                mma_bf16(acc[nt], al, bhf[nt][s]);
            }
        }

        int d0 = dsts[g], d1 = dsts[g + 8];
        #pragma unroll
        for (int nt = 0; nt < 2; nt++) {
            int col = wid * 16 + nt * 8 + tg * 2;
            if (d0 >= 0) {
                atomicAdd(&Y[(size_t)d0 * DD + col],     acc[nt][0]);
                atomicAdd(&Y[(size_t)d0 * DD + col + 1], acc[nt][1]);
            }
            if (d1 >= 0) {
                atomicAdd(&Y[(size_t)d1 * DD + col],     acc[nt][2]);
                atomicAdd(&Y[(size_t)d1 * DD + col + 1], acc[nt][3]);
            }
        }
    }
}

// ---------------- launcher (single stream, 10 launches) ----------------
extern "C" void kernel_launch(void* const* d_in, const int* in_sizes, int n_in,
                              void* d_out, int out_size) {
    const int*   entity = (const int*)d_in[0];
    const int*   eidx   = (const int*)d_in[1];
    const int*   etype  = (const int*)d_in[2];
    const float* emb    = (const float*)d_in[3];
    const float* basis1 = (const float*)d_in[4];
    const float* att1   = (const float*)d_in[5];
    const float* w1     = (const float*)d_in[6];
    const float* root1  = (const float*)d_in[7];
    const float* bias1  = (const float*)d_in[8];
    const float* basis2 = (const float*)d_in[9];
    const float* att2   = (const float*)d_in[10];
    const float* w2     = (const float*)d_in[11];
    const float* root2  = (const float*)d_in[12];
    const float* bias2  = (const float*)d_in[13];
    float* out = (float*)d_out;
    const int* src = eidx;
    const int* dst = eidx + EE;

    float *pX = nullptr, *pH = nullptr, *pW1 = nullptr, *pW2 = nullptr, *pD0 = nullptr, *pD1 = nullptr;
    cudaGetSymbolAddress((void**)&pX, g_X);
    cudaGetSymbolAddress((void**)&pH, g_H);
    cudaGetSymbolAddress((void**)&pW1, g_W1);
    cudaGetSymbolAddress((void**)&pW2, g_W2);
    cudaGetSymbolAddress((void**)&pD0, g_denom0);
    cudaGetSymbolAddress((void**)&pD1, g_denom1);

    cudaFuncSetAttribute(k_wbuild, cudaFuncAttributeMaxDynamicSharedMemorySize, WB_SMEM);

    const int NVEC = NN * DD / 4;
    const dim3 rootGrid(3, (NN + 63) / 64);       // x==2 slice = scale prep
    const int ALPHA_BLOCKS = EE / 4 / 8;          // 1024 blocks

    k_gather_init<<<(NVEC + 255) / 256, 256>>>(entity, emb, etype);
    k_scanplace<<<GB, 512>>>(etype, src, dst);

    // ---- layer 1 ----
    k_wbuild<<<dim3(128, 2), 256, WB_SMEM>>>(att1, basis1, pW1, RR);
    k_alpha_exp<<<ALPHA_BLOCKS, 256>>>(pX, src, dst, etype, w1, pD0, 0);
    k_root<<<rootGrid, 128>>>(pX, root1, bias1, pH, NN, 0, pD0);
    k_msg<<<RR, 256>>>(pX, pH, 0, pW1);

    // ---- layer 2 (relu applied on read of H) ----
    k_wbuild<<<dim3(128, 2), 256, WB_SMEM>>>(att2, basis2, pW2, RR);
    k_alpha_exp<<<ALPHA_BLOCKS, 256>>>(pH, src, dst, etype, w2, pD1, 1);
    k_root<<<rootGrid, 128>>>(pH, root2, bias2, out, NN, 1, pD1);
    k_msg<<<RR, 256>>>(pH, out, 1, pW2);
}

// round 15
// speedup vs baseline: 1.4129x; 1.0790x over previous
#include <cuda_runtime.h>
#include <cuda_bf16.h>
#include <cstdint>

#define NN 20000
#define DD 128
#define EE 32768
#define RR 474
#define BB 64
#define GB 32
#define EPB (EE / GB)

// ---------------- device scratch ----------------
__device__ float g_X[NN * DD];
__device__ float g_H[NN * DD];
__device__ float g_W1[RR * DD * DD];
__device__ float g_W2[RR * DD * DD];
__device__ float g_alpha[EE];
__device__ float g_denom0[NN];
__device__ float g_denom1[NN];
__device__ int   g_bh[GB * RR];
__device__ int   g_offs[RR + 1];
__device__ int   g_order[EE];
__device__ int   g_esrc[EE];
__device__ int   g_edst[EE];
__device__ float g_escl[EE];

// ---------------- mma / ldmatrix helpers ----------------
__device__ __forceinline__ void mma_bf16(float* d, const uint32_t* a, const uint32_t* b) {
    asm volatile(
        "mma.sync.aligned.m16n8k16.row.col.f32.bf16.bf16.f32 "
        "{%0,%1,%2,%3}, {%4,%5,%6,%7}, {%8,%9}, {%0,%1,%2,%3};"
        : "+f"(d[0]), "+f"(d[1]), "+f"(d[2]), "+f"(d[3])
        : "r"(a[0]), "r"(a[1]), "r"(a[2]), "r"(a[3]), "r"(b[0]), "r"(b[1]));
}
__device__ __forceinline__ void ldsm_x4(uint32_t* r, const void* p) {
    uint32_t addr = (uint32_t)__cvta_generic_to_shared(p);
    asm volatile("ldmatrix.sync.aligned.m8n8.x4.shared.b16 {%0,%1,%2,%3}, [%4];"
        : "=r"(r[0]), "=r"(r[1]), "=r"(r[2]), "=r"(r[3]) : "r"(addr));
}
__device__ __forceinline__ uint32_t pack2_bf16(float a, float b) {
    __nv_bfloat162 p = __floats2bfloat162_rn(a, b);
    return *reinterpret_cast<uint32_t*>(&p);
}
__device__ __forceinline__ void split_bf16(float v, __nv_bfloat16& h, float& lo) {
    h = __float2bfloat16(v);
    lo = v - __bfloat162float(h);
}

// ================= W build: C[M,16384] = A[M,64] @ B[64,16384] =================
#define WB_STRIDE 72
#define WB_B_HI 0
#define WB_B_LO (128 * WB_STRIDE * 2)
#define WB_A_HI (2 * 128 * WB_STRIDE * 2)
#define WB_A_LO (2 * 128 * WB_STRIDE * 2 + 64 * WB_STRIDE * 2)
#define WB_SMEM (2 * 128 * WB_STRIDE * 2 + 2 * 64 * WB_STRIDE * 2)  // 55296

__global__ void __launch_bounds__(256, 2)
k_wbuild(const float* __restrict__ A, const float* __restrict__ B,
         float* __restrict__ C, int M) {
    extern __shared__ char smem[];
    __nv_bfloat16* sBh = (__nv_bfloat16*)(smem + WB_B_HI);
    __nv_bfloat16* sBl = (__nv_bfloat16*)(smem + WB_B_LO);
    __nv_bfloat16* sAh = (__nv_bfloat16*)(smem + WB_A_HI);
    __nv_bfloat16* sAl = (__nv_bfloat16*)(smem + WB_A_LO);

    int t = threadIdx.x;
    int n0 = blockIdx.x * 128;

    #pragma unroll
    for (int e = t; e < 64 * 128; e += 256) {
        int k = e >> 7, n = e & 127;
        float v = B[(size_t)k * 16384 + n0 + n];
        __nv_bfloat16 h; float lo;
        split_bf16(v, h, lo);
        sBh[n * WB_STRIDE + k] = h;
        sBl[n * WB_STRIDE + k] = __float2bfloat16(lo);
    }

    int wid = t >> 5, lane = t & 31;
    int warpM = wid >> 2, warpN = wid & 3;
    int g = lane >> 2, tg = lane & 3;
    int aRow = (lane & 15);
    int aColSel = ((lane >> 4) << 3);
    int bN = ((lane >> 4) << 3) + (lane & 7);
    int bKSel = (((lane >> 3) & 1) << 3);

    for (int mt4 = 0; mt4 < 4; mt4++) {
        int m0 = blockIdx.y * 256 + mt4 * 64;
        __syncthreads();
        #pragma unroll
        for (int e = t; e < 64 * 64; e += 256) {
            int m = e >> 6, k = e & 63;
            float v = (m0 + m < M) ? A[(m0 + m) * 64 + k] : 0.f;
            __nv_bfloat16 h; float lo;
            split_bf16(v, h, lo);
            sAh[m * WB_STRIDE + k] = h;
            sAl[m * WB_STRIDE + k] = __float2bfloat16(lo);
        }
        __syncthreads();

        float acc[2][4][4];
        #pragma unroll
        for (int i = 0; i < 2; i++)
            #pragma unroll
            for (int j = 0; j < 4; j++)
                #pragma unroll
                for (int q = 0; q < 4; q++) acc[i][j][q] = 0.f;

        #pragma unroll
        for (int ks = 0; ks < 4; ks++) {
            int k0 = ks * 16;
            uint32_t ah[2][4], al[2][4];
            #pragma unroll
            for (int mt = 0; mt < 2; mt++) {
                int row = warpM * 32 + mt * 16 + aRow;
                ldsm_x4(ah[mt], &sAh[row * WB_STRIDE + k0 + aColSel]);
                ldsm_x4(al[mt], &sAl[row * WB_STRIDE + k0 + aColSel]);
            }
            uint32_t bh[4][2], bl[4][2];
            #pragma unroll
            for (int np = 0; np < 2; np++) {
                int n = warpN * 32 + np * 16 + bN;
                uint32_t tmp[4];
                ldsm_x4(tmp, &sBh[n * WB_STRIDE + k0 + bKSel]);
                bh[np * 2][0] = tmp[0]; bh[np * 2][1] = tmp[1];
                bh[np * 2 + 1][0] = tmp[2]; bh[np * 2 + 1][1] = tmp[3];
                ldsm_x4(tmp, &sBl[n * WB_STRIDE + k0 + bKSel]);
                bl[np * 2][0] = tmp[0]; bl[np * 2][1] = tmp[1];
                bl[np * 2 + 1][0] = tmp[2]; bl[np * 2 + 1][1] = tmp[3];
            }
            #pragma unroll
            for (int mt = 0; mt < 2; mt++)
                #pragma unroll
                for (int nt = 0; nt < 4; nt++) {
                    mma_bf16(acc[mt][nt], ah[mt], bh[nt]);
                    mma_bf16(acc[mt][nt], ah[mt], bl[nt]);
                    mma_bf16(acc[mt][nt], al[mt], bh[nt]);
                }
        }

        #pragma unroll
        for (int mt = 0; mt < 2; mt++) {
            int r0 = m0 + warpM * 32 + mt * 16 + g;
            #pragma unroll
            for (int nt = 0; nt < 4; nt++) {
                int col = n0 + warpN * 32 + nt * 8 + tg * 2;
                if (r0 < M)
                    *(float2*)&C[(size_t)r0 * 16384 + col] = make_float2(acc[mt][nt][0], acc[mt][nt][1]);
                if (r0 + 8 < M)
                    *(float2*)&C[(size_t)(r0 + 8) * 16384 + col] = make_float2(acc[mt][nt][2], acc[mt][nt][3]);
            }
        }
    }
}

// ================= root GEMM + fused per-edge scale precompute =================
#define RT_STRIDE 136
__global__ void __launch_bounds__(128, 4)
k_root(const float* __restrict__ A, const float* __restrict__ Broot,
       const float* __restrict__ bias, float* __restrict__ C, int M, int relu_in,
       const float* __restrict__ denom) {
    int t = threadIdx.x;

    if (blockIdx.x == 2) {
        int j = blockIdx.y * 128 + t;
        if (j < EE) {
            int e = g_order[j];
            g_escl[j] = g_alpha[e] / denom[g_edst[j]];
        }
        return;
    }

    int n_base = blockIdx.x * 64;
    int m0 = blockIdx.y * 64;
    int wid = t >> 5, lane = t & 31;
    int g = lane >> 2, tg = lane & 3;

    uint32_t bhf[2][8][2], blf[2][8][2];
    #pragma unroll
    for (int nt = 0; nt < 2; nt++) {
        int n = n_base + wid * 16 + nt * 8 + g;
        #pragma unroll
        for (int s = 0; s < 8; s++) {
            int k0 = s * 16 + tg * 2;
            float w0 = Broot[(k0 + 0) * 128 + n];
            float w1 = Broot[(k0 + 1) * 128 + n];
            float w2 = Broot[(k0 + 8) * 128 + n];
            float w3 = Broot[(k0 + 9) * 128 + n];
            __nv_bfloat16 h0, h1, h2, h3; float l0, l1, l2, l3;
            split_bf16(w0, h0, l0); split_bf16(w1, h1, l1);
            split_bf16(w2, h2, l2); split_bf16(w3, h3, l3);
            bhf[nt][s][0] = pack2_bf16(__bfloat162float(h0), __bfloat162float(h1));
            bhf[nt][s][1] = pack2_bf16(__bfloat162float(h2), __bfloat162float(h3));
            blf[nt][s][0] = pack2_bf16(l0, l1);
            blf[nt][s][1] = pack2_bf16(l2, l3);
        }
    }

    __shared__ __align__(16) __nv_bfloat16 s_ah[64][RT_STRIDE];
    __shared__ __align__(16) __nv_bfloat16 s_al[64][RT_STRIDE];

    #pragma unroll
    for (int e = t; e < 64 * 128; e += 128) {
        int row = e >> 7, col = e & 127;
        float v = (m0 + row < M) ? A[(size_t)(m0 + row) * 128 + col] : 0.f;
        if (relu_in) v = fmaxf(v, 0.f);
        __nv_bfloat16 h; float lo;
        split_bf16(v, h, lo);
        s_ah[row][col] = h;
        s_al[row][col] = __float2bfloat16(lo);
    }
    __syncthreads();

    float2 biasv[2];
    #pragma unroll
    for (int nt = 0; nt < 2; nt++) {
        int col = n_base + wid * 16 + nt * 8 + tg * 2;
        biasv[nt] = make_float2(bias[col], bias[col + 1]);
    }

    int aRow = (lane & 15);
    int aColSel = ((lane >> 4) << 3);

    #pragma unroll
    for (int mt = 0; mt < 4; mt++) {
        float acc[2][4];
        #pragma unroll
        for (int nt = 0; nt < 2; nt++)
            #pragma unroll
            for (int q = 0; q < 4; q++) acc[nt][q] = 0.f;

        #pragma unroll
        for (int s = 0; s < 8; s++) {
            int row = mt * 16 + aRow;
            int col = s * 16 + aColSel;
            uint32_t ah[4], al[4];
            ldsm_x4(ah, &s_ah[row][col]);
            ldsm_x4(al, &s_al[row][col]);
            #pragma unroll
            for (int nt = 0; nt < 2; nt++) {
                mma_bf16(acc[nt], ah, bhf[nt][s]);
                mma_bf16(acc[nt], ah, blf[nt][s]);
                mma_bf16(acc[nt], al, bhf[nt][s]);
            }
        }

        int r0 = m0 + mt * 16 + g, r1 = r0 + 8;
        #pragma unroll
        for (int nt = 0; nt < 2; nt++) {
            int col = n_base + wid * 16 + nt * 8 + tg * 2;
            if (r0 < M)
                *(float2*)&C[(size_t)r0 * 128 + col] =
                    make_float2(acc[nt][0] + biasv[nt].x, acc[nt][1] + biasv[nt].y);
            if (r1 < M)
                *(float2*)&C[(size_t)r1 * 128 + col] =
                    make_float2(acc[nt][2] + biasv[nt].x, acc[nt][3] + biasv[nt].y);
        }
    }
}

// ---------------- gather + denom init + per-slice histogram ----------------
__global__ void k_gather_init(const int* __restrict__ entity, const float* __restrict__ emb,
                              const int* __restrict__ etype) {
    __shared__ int h[RR];
    int t = threadIdx.x, b = blockIdx.x;
    bool histBlock = (b < GB);
    if (histBlock) {
        for (int i = t; i < RR; i += 256) h[i] = 0;
        __syncthreads();
        int base = b * EPB;
        for (int i = t; i < EPB; i += 256) atomicAdd(&h[etype[base + i]], 1);
    }

    int g = b * 256 + t;
    if (g < NN) { g_denom0[g] = 0.f; g_denom1[g] = 0.f; }
    if (g < NN * DD / 4) {
        int elem = g * 4;
        int n = elem >> 7, d = elem & 127;
        int idx = entity[n];
        *(float4*)&g_X[elem] = *(const float4*)&emb[idx * DD + d];
    }

    if (histBlock) {
        __syncthreads();
        for (int i = t; i < RR; i += 256) g_bh[b * RR + i] = h[i];
    }
}

// ---------------- fused scan + place (also writes sorted src/dst) ----------------
__global__ void __launch_bounds__(512, 2)
k_scanplace(const int* __restrict__ etype, const int* __restrict__ src,
            const int* __restrict__ dst) {
    __shared__ int tot[512];
    __shared__ int cur[RR];
    int t = threadIdx.x, b = blockIdx.x;

    int sum = 0, pre = 0;
    if (t < RR) {
        #pragma unroll 8
        for (int bb = 0; bb < GB; bb++) {
            int c = g_bh[bb * RR + t];
            if (bb < b) pre += c;
            sum += c;
        }
    }
    tot[t] = (t < RR) ? sum : 0;
    __syncthreads();
    #pragma unroll
    for (int off = 1; off < 512; off <<= 1) {
        int v = (t >= off) ? tot[t - off] : 0;
        __syncthreads();
        tot[t] += v;
        __syncthreads();
    }
    if (t < RR) {
        cur[t] = (tot[t] - sum) + pre;
        if (b == 0) g_offs[t + 1] = tot[t];
    }
    if (b == 0 && t == 0) g_offs[0] = 0;
    __syncthreads();

    int base = b * EPB;
    for (int i = t; i < EPB; i += 512) {
        int e = base + i;
        int p = atomicAdd(&cur[etype[e]], 1);
        g_order[p] = e;
        g_esrc[p] = src[e];
        g_edst[p] = dst[e];
    }
}

// ---------------- fused logits+exp+denom: 4 edges per warp ----------------
__global__ void k_alpha_exp(const float* __restrict__ X, const int* __restrict__ src,
                            const int* __restrict__ dst, const int* __restrict__ etype,
                            const float* __restrict__ wt, float* __restrict__ denom,
                            int relu_in) {
    int warpId = (blockIdx.x * blockDim.x + threadIdx.x) >> 5;
    int e0 = warpId * 4;
    if (e0 >= EE) return;
    int lane = threadIdx.x & 31;

    int s[4], d[4], r[4];
    #pragma unroll
    for (int j = 0; j < 4; j++) {
        s[j] = src[e0 + j]; d[j] = dst[e0 + j]; r[j] = etype[e0 + j];
    }
    float4 xi[4], xj[4], w[4];
    #pragma unroll
    for (int j = 0; j < 4; j++) {
        xi[j] = *(const float4*)&X[(size_t)d[j] * DD + lane * 4];
        xj[j] = *(const float4*)&X[(size_t)s[j] * DD + lane * 4];
        w[j]  = *(const float4*)&wt[(size_t)r[j] * DD + lane * 4];
    }
    #pragma unroll
    for (int j = 0; j < 4; j++) {
        float4 a = xi[j], bq = xj[j];
        if (relu_in) {
            a.x = fmaxf(a.x, 0.f); a.y = fmaxf(a.y, 0.f);
            a.z = fmaxf(a.z, 0.f); a.w = fmaxf(a.w, 0.f);
            bq.x = fmaxf(bq.x, 0.f); bq.y = fmaxf(bq.y, 0.f);
            bq.z = fmaxf(bq.z, 0.f); bq.w = fmaxf(bq.w, 0.f);
        }
        float v = a.x * w[j].x * bq.x + a.y * w[j].y * bq.y
                + a.z * w[j].z * bq.z + a.w * w[j].w * bq.w;
        #pragma unroll
        for (int off = 16; off; off >>= 1) v += __shfl_xor_sync(0xffffffffu, v, off);
        if (lane == 0) {
            float e = expf(v);
            g_alpha[e0 + j] = e;
            atomicAdd(&denom[d[j]], e);
        }
    }
}

// ---------------- per-type messages on tensor cores ----------------
#define MSG_STRIDE 136
__global__ void __launch_bounds__(256, 2)
k_msg(const float* __restrict__ Xin, float* __restrict__ Y,
      int relu_in, const float* __restrict__ Wbuf) {
    int r = blockIdx.x;
    int base = g_offs[r];
    int cnt = g_offs[r + 1] - base;
    if (cnt == 0) return;
    int t = threadIdx.x, wid = t >> 5, lane = t & 31;
    int g = lane >> 2, tg = lane & 3;

    const float* Wr = Wbuf + (size_t)r * 16384;
    uint32_t bhf[2][8][2], blf[2][8][2];
    #pragma unroll
    for (int nt = 0; nt < 2; nt++) {
        int n = wid * 16 + nt * 8 + g;
        #pragma unroll
        for (int s = 0; s < 8; s++) {
            int k0 = s * 16 + tg * 2;
            float w0 = Wr[(k0 + 0) * 128 + n];
            float w1 = Wr[(k0 + 1) * 128 + n];
            float w2 = Wr[(k0 + 8) * 128 + n];
            float w3 = Wr[(k0 + 9) * 128 + n];
            __nv_bfloat16 h0, h1, h2, h3; float l0, l1, l2, l3;
            split_bf16(w0, h0, l0); split_bf16(w1, h1, l1);
            split_bf16(w2, h2, l2); split_bf16(w3, h3, l3);
            bhf[nt][s][0] = pack2_bf16(__bfloat162float(h0), __bfloat162float(h1));
            bhf[nt][s][1] = pack2_bf16(__bfloat162float(h2), __bfloat162float(h3));
            blf[nt][s][0] = pack2_bf16(l0, l1);
            blf[nt][s][1] = pack2_bf16(l2, l3);
        }
    }

    __shared__ __align__(16) __nv_bfloat16 s_xh[16][MSG_STRIDE];
    __shared__ __align__(16) __nv_bfloat16 s_xl[16][MSG_STRIDE];
    __shared__ int   dsts[16];
    __shared__ int   srcs[16];
    __shared__ float scl[16];

    int aRow = (lane & 15);
    int aColSel = ((lane >> 4) << 3);

    for (int g0 = 0; g0 < cnt; g0 += 16) {
        __syncthreads();
        if (t < 16) {
            int j = g0 + t;
            if (j < cnt) {
                dsts[t] = g_edst[base + j];
                srcs[t] = g_esrc[base + j];
                scl[t]  = g_escl[base + j];
            } else { dsts[t] = -1; srcs[t] = 0; scl[t] = 0.f; }
        }
        __syncthreads();
        #pragma unroll
        for (int j4 = 0; j4 < 16; j4 += 4) {
            int j = j4 + (t >> 6);
            int i = (t & 63) * 2;
            float2 v = *(const float2*)&Xin[(size_t)srcs[j] * DD + i];
            if (relu_in) { v.x = fmaxf(v.x, 0.f); v.y = fmaxf(v.y, 0.f); }
            float sc = scl[j];
            v.x *= sc; v.y *= sc;
            __nv_bfloat16 h0, h1; float l0, l1;
            split_bf16(v.x, h0, l0);
            split_bf16(v.y, h1, l1);
            *(uint32_t*)&s_xh[j][i] = pack2_bf16(__bfloat162float(h0), __bfloat162float(h1));
            *(uint32_t*)&s_xl[j][i] = pack2_bf16(l0, l1);
        }
        __syncthreads();

        float acc[2][4];
        #pragma unroll
        for (int nt = 0; nt < 2; nt++)
            #pragma unroll
            for (int q = 0; q < 4; q++) acc[nt][q] = 0.f;

        #pragma unroll
        for (int s = 0; s < 8; s++) {
            int col = s * 16 + aColSel;
            uint32_t ah[4], al[4];
            ldsm_x4(ah, &s_xh[aRow][col]);
            ldsm_x4(al, &s_xl[aRow][col]);
            #pragma unroll
            for (int nt = 0; nt < 2; nt++) {
                mma_bf16(acc[nt], ah, bhf[nt][s]);
                mma_bf16(acc[nt], ah, blf[nt][s]);
                mma_bf16(acc[nt], al, bhf[nt][s]);
            }
        }

        int d0 = dsts[g], d1 = dsts[g + 8];
        #pragma unroll
        for (int nt = 0; nt < 2; nt++) {
            int col = wid * 16 + nt * 8 + tg * 2;
            if (d0 >= 0) {
                atomicAdd(&Y[(size_t)d0 * DD + col],     acc[nt][0]);
                atomicAdd(&Y[(size_t)d0 * DD + col + 1], acc[nt][1]);
            }
            if (d1 >= 0) {
                atomicAdd(&Y[(size_t)d1 * DD + col],     acc[nt][2]);
                atomicAdd(&Y[(size_t)d1 * DD + col + 1], acc[nt][3]);
            }
        }
    }
}

// ---------------- launcher: forked-stream graph ----------------
extern "C" void kernel_launch(void* const* d_in, const int* in_sizes, int n_in,
                              void* d_out, int out_size) {
    const int*   entity = (const int*)d_in[0];
    const int*   eidx   = (const int*)d_in[1];
    const int*   etype  = (const int*)d_in[2];
    const float* emb    = (const float*)d_in[3];
    const float* basis1 = (const float*)d_in[4];
    const float* att1   = (const float*)d_in[5];
    const float* w1     = (const float*)d_in[6];
    const float* root1  = (const float*)d_in[7];
    const float* bias1  = (const float*)d_in[8];
    const float* basis2 = (const float*)d_in[9];
    const float* att2   = (const float*)d_in[10];
    const float* w2     = (const float*)d_in[11];
    const float* root2  = (const float*)d_in[12];
    const float* bias2  = (const float*)d_in[13];
    float* out = (float*)d_out;
    const int* src = eidx;
    const int* dst = eidx + EE;

    float *pX = nullptr, *pH = nullptr, *pW1 = nullptr, *pW2 = nullptr, *pD0 = nullptr, *pD1 = nullptr;
    cudaGetSymbolAddress((void**)&pX, g_X);
    cudaGetSymbolAddress((void**)&pH, g_H);
    cudaGetSymbolAddress((void**)&pW1, g_W1);
    cudaGetSymbolAddress((void**)&pW2, g_W2);
    cudaGetSymbolAddress((void**)&pD0, g_denom0);
    cudaGetSymbolAddress((void**)&pD1, g_denom1);

    cudaFuncSetAttribute(k_wbuild, cudaFuncAttributeMaxDynamicSharedMemorySize, WB_SMEM);

    const int NVEC = NN * DD / 4;
    const dim3 rootGrid(3, (NN + 63) / 64);
    const int ALPHA_BLOCKS = EE / 4 / 8;

    static cudaStream_t sB = nullptr, sC = nullptr;
    static cudaEvent_t evFork = nullptr, evGather = nullptr, evB1 = nullptr, evB2 = nullptr, evSP = nullptr;
    if (!sB) {
        cudaStreamCreateWithFlags(&sB, cudaStreamNonBlocking);
        cudaStreamCreateWithFlags(&sC, cudaStreamNonBlocking);
        cudaEventCreateWithFlags(&evFork, cudaEventDisableTiming);
        cudaEventCreateWithFlags(&evGather, cudaEventDisableTiming);
        cudaEventCreateWithFlags(&evB1, cudaEventDisableTiming);
        cudaEventCreateWithFlags(&evB2, cudaEventDisableTiming);
        cudaEventCreateWithFlags(&evSP, cudaEventDisableTiming);
    }

    // fork stream B at entry (wbuilds have no input deps)
    cudaEventRecord(evFork, 0);
    cudaStreamWaitEvent(sB, evFork, 0);
    k_wbuild<<<dim3(128, 2), 256, WB_SMEM, sB>>>(att1, basis1, pW1, RR);
    cudaEventRecord(evB1, sB);
    k_wbuild<<<dim3(128, 2), 256, WB_SMEM, sB>>>(att2, basis2, pW2, RR);
    cudaEventRecord(evB2, sB);

    // main: gather (also produces histogram for scanplace)
    k_gather_init<<<(NVEC + 255) / 256, 256>>>(entity, emb, etype);
    cudaEventRecord(evGather, 0);

    // stream C: scanplace after gather
    cudaStreamWaitEvent(sC, evGather, 0);
    k_scanplace<<<GB, 512, 0, sC>>>(etype, src, dst);
    cudaEventRecord(evSP, sC);

    // ---- layer 1 ----
    k_alpha_exp<<<ALPHA_BLOCKS, 256>>>(pX, src, dst, etype, w1, pD0, 0);
    cudaStreamWaitEvent(0, evSP, 0);       // root's scale-prep needs g_order/g_edst
    k_root<<<rootGrid, 128>>>(pX, root1, bias1, pH, NN, 0, pD0);
    cudaStreamWaitEvent(0, evB1, 0);       // msg needs W1
    k_msg<<<RR, 256>>>(pX, pH, 0, pW1);

    // ---- layer 2 ----
    k_alpha_exp<<<ALPHA_BLOCKS, 256>>>(pH, src, dst, etype, w2, pD1, 1);
    k_root<<<rootGrid, 128>>>(pH, root2, bias2, out, NN, 1, pD1);
    cudaStreamWaitEvent(0, evB2, 0);       // msg needs W2
    k_msg<<<RR, 256>>>(pH, out, 1, pW2);
}